// round 1
// baseline (speedup 1.0000x reference)
#include <cuda_runtime.h>
#include <math.h>

// Problem constants (fixed shapes)
namespace {
constexpr int Nn   = 65536;    // B*NPG nodes per side
constexpr int Cc   = 256;      // feature dim
constexpr int Ee   = 1048576;  // edges per edge set
constexpr int Bb   = 16;       // batch
constexpr int NPGv = 4096;     // nodes per graph
constexpr int Kk   = 1024;     // top-k
constexpr int NT   = 131072;   // 2*N
constexpr int SPLIT = 8;       // pooling row splits per (side,batch)
}

// Scratch (device globals: no allocation allowed)
__device__ float    g_k[NT];
__device__ float    g_q[NT];
__device__ float    g_v[NT];
__device__ unsigned g_menc[NT];   // encoded segment max
__device__ float    g_den[NT];
__device__ float    g_num[NT];
__device__ float    g_wt[NT];     // pooling weight per node (tanh(score)/K or 0)

// ---- float <-> order-preserving uint ------------------------------------
__device__ __forceinline__ unsigned encf(float f) {
    unsigned u = __float_as_uint(f);
    return (u & 0x80000000u) ? ~u : (u | 0x80000000u);
}
__device__ __forceinline__ float decf(unsigned e) {
    unsigned u = (e & 0x80000000u) ? (e ^ 0x80000000u) : ~e;
    return __uint_as_float(u);
}

// ---- init: zero accumulators + output -----------------------------------
__global__ void init_kernel(float* __restrict__ out) {
    int i = blockIdx.x * blockDim.x + threadIdx.x;
    if (i < NT) {
        g_menc[i] = 0u;       // 0 < encf(any finite) -> identity for max
        g_den[i]  = 0.f;
        g_num[i]  = 0.f;
    }
    if (i < Bb * 2 * Cc) out[i] = 0.f;
}

// ---- kqv: per-node 3 dot products (warp per node) ------------------------
__global__ void kqv_kernel(const float* __restrict__ x_i, const float* __restrict__ x_d,
                           const float* __restrict__ w_i, const float* __restrict__ b_i,
                           const float* __restrict__ w_d, const float* __restrict__ b_d) {
    __shared__ float sw[Cc * 3];
    __shared__ float sb[3];
    int node0 = blockIdx.x * 8;          // 8 warps per block, one node per warp
    int side  = (node0 >= Nn) ? 1 : 0;   // N % 8 == 0 -> block never straddles
    const float* w = side ? w_d : w_i;
    const float* bb = side ? b_d : b_i;
    for (int i = threadIdx.x; i < Cc * 3; i += blockDim.x) sw[i] = w[i];
    if (threadIdx.x < 3) sb[threadIdx.x] = bb[threadIdx.x];
    __syncthreads();

    int warp = threadIdx.x >> 5;
    int lane = threadIdx.x & 31;
    int node = node0 + warp;
    const float* x = side ? (x_d + (long long)(node - Nn) * Cc)
                          : (x_i + (long long)node * Cc);
    float s0 = 0.f, s1 = 0.f, s2 = 0.f;
#pragma unroll
    for (int h = 0; h < 2; ++h) {
        int c = lane * 4 + h * 128;
        float4 xv = *reinterpret_cast<const float4*>(x + c);
        s0 += xv.x * sw[(c + 0) * 3 + 0] + xv.y * sw[(c + 1) * 3 + 0]
            + xv.z * sw[(c + 2) * 3 + 0] + xv.w * sw[(c + 3) * 3 + 0];
        s1 += xv.x * sw[(c + 0) * 3 + 1] + xv.y * sw[(c + 1) * 3 + 1]
            + xv.z * sw[(c + 2) * 3 + 1] + xv.w * sw[(c + 3) * 3 + 1];
        s2 += xv.x * sw[(c + 0) * 3 + 2] + xv.y * sw[(c + 1) * 3 + 2]
            + xv.z * sw[(c + 2) * 3 + 2] + xv.w * sw[(c + 3) * 3 + 2];
    }
#pragma unroll
    for (int o = 16; o; o >>= 1) {
        s0 += __shfl_down_sync(0xFFFFFFFFu, s0, o);
        s1 += __shfl_down_sync(0xFFFFFFFFu, s1, o);
        s2 += __shfl_down_sync(0xFFFFFFFFu, s2, o);
    }
    if (lane == 0) {
        g_k[node] = s0 + sb[0];
        g_q[node] = s1 + sb[1];
        g_v[node] = s2 + sb[2];
    }
}

// ---- edge pass 1: segment max of logits ----------------------------------
__global__ void edge_max_kernel(const int* __restrict__ ei0, const int* __restrict__ ei1,
                                const int* __restrict__ ei2,
                                const float* __restrict__ krel_w, const float* __restrict__ krel_b,
                                const float* __restrict__ p_rel) {
    // blocks-per-set = E/256 = 4096
    int t = blockIdx.x >> 12;                                   // 0,1,2 (uniform per block)
    int i = ((blockIdx.x & 4095) << 8) | threadIdx.x;
    const int* ei = (t == 0) ? ei0 : ((t == 1) ? ei1 : ei2);
    int s = ei[i];
    int d = ei[Ee + i];
    int sbase = (t == 1) ? Nn : 0;
    int dbase = (t == 0) ? Nn : 0;
    float ke    = g_k[sbase + s] * krel_w[t] + krel_b[t];
    float logit = g_q[dbase + d] * ke * p_rel[t];
    atomicMax(&g_menc[dbase + d], encf(logit));
}

// ---- edge pass 2: exp-sum and weighted value sum --------------------------
__global__ void edge_sum_kernel(const int* __restrict__ ei0, const int* __restrict__ ei1,
                                const int* __restrict__ ei2,
                                const float* __restrict__ krel_w, const float* __restrict__ krel_b,
                                const float* __restrict__ vrel_w, const float* __restrict__ vrel_b,
                                const float* __restrict__ p_rel) {
    int t = blockIdx.x >> 12;
    int i = ((blockIdx.x & 4095) << 8) | threadIdx.x;
    const int* ei = (t == 0) ? ei0 : ((t == 1) ? ei1 : ei2);
    int s = ei[i];
    int d = ei[Ee + i];
    int sbase = (t == 1) ? Nn : 0;
    int dbase = (t == 0) ? Nn : 0;
    int dg = dbase + d;
    float ke    = g_k[sbase + s] * krel_w[t] + krel_b[t];
    float ve    = g_v[sbase + s] * vrel_w[t] + vrel_b[t];
    float logit = g_q[dg] * ke * p_rel[t];
    float m  = decf(g_menc[dg]);
    float ex = expf(logit - m);
    atomicAdd(&g_den[dg], ex);
    atomicAdd(&g_num[dg], ex * ve);
}

// ---- score + per-batch top-K selection -> pooling weights -----------------
__global__ void select_kernel(const float* __restrict__ w_out_i, const float* __restrict__ b_out_i,
                              const float* __restrict__ w_out_d, const float* __restrict__ b_out_d) {
    __shared__ unsigned skey[NPGv];
    __shared__ float    sval[NPGv];
    __shared__ int      scnt;
    int side = blockIdx.x >> 4;      // 0..1
    int b    = blockIdx.x & 15;      // 0..15
    int base = side * Nn + b * NPGv;
    float wo = side ? w_out_d[0] : w_out_i[0];
    float bo = side ? b_out_d[0] : b_out_i[0];

    for (int j = threadIdx.x; j < NPGv; j += blockDim.x) {
        float den = g_den[base + j];
        float a   = (den > 0.f) ? (g_num[base + j] / den) : 0.f;   // empty segment -> 0
        float z   = a * wo + bo;
        float sc  = 0.5f * z * (1.f + erff(z * 0.70710678118654752f));  // exact gelu
        sval[j] = sc;
        skey[j] = encf(sc);
    }
    __syncthreads();

    int lane = threadIdx.x & 31;
    auto count_ge = [&](unsigned key) -> int {
        if (threadIdx.x == 0) scnt = 0;
        __syncthreads();
        int c = 0;
        for (int j = threadIdx.x; j < NPGv; j += blockDim.x) c += (skey[j] >= key) ? 1 : 0;
#pragma unroll
        for (int o = 16; o; o >>= 1) c += __shfl_down_sync(0xFFFFFFFFu, c, o);
        if (lane == 0) atomicAdd(&scnt, c);
        __syncthreads();
        int r = scnt;
        __syncthreads();
        return r;
    };

    // largest thr with count(key >= thr) >= K (binary search on key space)
    unsigned lo = 0u, hi = 0xFFFFFFFFu;
    while (lo < hi) {
        unsigned mid = (unsigned)((((unsigned long long)lo + (unsigned long long)hi) + 1ull) >> 1);
        if (count_ge(mid) >= Kk) lo = mid; else hi = mid - 1u;
    }
    unsigned thr = lo;
    int cnt_gt = (thr == 0xFFFFFFFFu) ? 0 : count_ge(thr + 1u);
    int need_eq = Kk - cnt_gt;

    for (int j = threadIdx.x; j < NPGv; j += blockDim.x) {
        unsigned key = skey[j];
        bool sel = key > thr;
        if (key == thr) {
            // tie-break by smallest index, matching lax.top_k
            int rank = 0;
            for (int j2 = 0; j2 < j; ++j2) rank += (skey[j2] == thr) ? 1 : 0;
            sel = rank < need_eq;
        }
        g_wt[base + j] = sel ? tanhf(sval[j]) * (1.f / (float)Kk) : 0.f;
    }
}

// ---- pooling: weighted sum of selected rows -------------------------------
__global__ void pool_kernel(const float* __restrict__ x_i, const float* __restrict__ x_d,
                            float* __restrict__ out) {
    __shared__ float sw[NPGv / SPLIT];   // 512
    int part = blockIdx.x & (SPLIT - 1);
    int sb   = blockIdx.x >> 3;          // SPLIT == 8
    int side = sb >> 4;
    int b    = sb & 15;
    int c    = threadIdx.x;              // 256 threads = one column each
    const float* x = side ? x_d : x_i;
    const int rows_per = NPGv / SPLIT;
    int r0 = part * rows_per;
    int nodebase = side * Nn + b * NPGv + r0;
    long long rowbase = (long long)(b * NPGv + r0) * Cc;

    for (int r = threadIdx.x; r < rows_per; r += blockDim.x) sw[r] = g_wt[nodebase + r];
    __syncthreads();

    float acc = 0.f;
    for (int r = 0; r < rows_per; ++r) {
        float w = sw[r];
        if (w != 0.f) acc += w * x[rowbase + (long long)r * Cc + c];
    }
    atomicAdd(&out[b * (2 * Cc) + side * Cc + c], acc);
}

// ---- launch ----------------------------------------------------------------
extern "C" void kernel_launch(void* const* d_in, const int* in_sizes, int n_in,
                              void* d_out, int out_size) {
    const float* x_inst     = (const float*)d_in[0];
    const float* x_data     = (const float*)d_in[1];
    const float* w_kqv_inst = (const float*)d_in[2];
    const float* b_kqv_inst = (const float*)d_in[3];
    const float* w_kqv_data = (const float*)d_in[4];
    const float* b_kqv_data = (const float*)d_in[5];
    const float* w_out_inst = (const float*)d_in[6];
    const float* b_out_inst = (const float*)d_in[7];
    const float* w_out_data = (const float*)d_in[8];
    const float* b_out_data = (const float*)d_in[9];
    const float* krel_w     = (const float*)d_in[10];
    const float* krel_b     = (const float*)d_in[11];
    const float* vrel_w     = (const float*)d_in[12];
    const float* vrel_b     = (const float*)d_in[13];
    const float* p_rel      = (const float*)d_in[14];
    const int*   ei_i2d     = (const int*)d_in[15];
    const int*   ei_d2i     = (const int*)d_in[16];
    const int*   ei_i2i     = (const int*)d_in[17];
    float* out = (float*)d_out;

    init_kernel<<<(NT + 255) / 256, 256>>>(out);
    kqv_kernel<<<(2 * Nn) / 8, 256>>>(x_inst, x_data, w_kqv_inst, b_kqv_inst,
                                      w_kqv_data, b_kqv_data);
    edge_max_kernel<<<3 * (Ee / 256), 256>>>(ei_i2d, ei_d2i, ei_i2i, krel_w, krel_b, p_rel);
    edge_sum_kernel<<<3 * (Ee / 256), 256>>>(ei_i2d, ei_d2i, ei_i2i, krel_w, krel_b,
                                             vrel_w, vrel_b, p_rel);
    select_kernel<<<2 * Bb, 512>>>(w_out_inst, b_out_inst, w_out_data, b_out_data);
    pool_kernel<<<2 * Bb * SPLIT, 256>>>(x_inst, x_data, out);
}

// round 2
// speedup vs baseline: 1.4045x; 1.4045x over previous
#include <cuda_runtime.h>
#include <math.h>

// Problem constants (fixed shapes)
namespace {
constexpr int Nn   = 65536;    // B*NPG nodes per side
constexpr int Cc   = 256;      // feature dim
constexpr int Ee   = 1048576;  // edges per edge set
constexpr int Bb   = 16;       // batch
constexpr int NPGv = 4096;     // nodes per graph
constexpr int Kk   = 1024;     // top-k
constexpr int NT   = 131072;   // 2*N
constexpr int SPLIT = 8;       // pooling row splits per (side,batch)
}

// Scratch (device globals: no allocation allowed)
__device__ float2 g_kv[NT];    // (k, v) packed -> one gather sector
__device__ float  g_q[NT];
__device__ float2 g_dn[NT];    // (num, den) packed -> one vector atomic
__device__ float  g_wt[NT];    // pooling weight per node (tanh(score)/K or 0)

// ---- float <-> order-preserving uint ------------------------------------
__device__ __forceinline__ unsigned encf(float f) {
    unsigned u = __float_as_uint(f);
    return (u & 0x80000000u) ? ~u : (u | 0x80000000u);
}

// ---- init: zero accumulators + output -----------------------------------
__global__ void init_kernel(float* __restrict__ out) {
    int i = blockIdx.x * blockDim.x + threadIdx.x;
    if (i < NT) g_dn[i] = make_float2(0.f, 0.f);
    if (i < Bb * 2 * Cc) out[i] = 0.f;
}

// ---- kqv: per-node 3 dot products (warp per node), conflict-free smem ----
__global__ void kqv_kernel(const float* __restrict__ x_i, const float* __restrict__ x_d,
                           const float* __restrict__ w_i, const float* __restrict__ b_i,
                           const float* __restrict__ w_d, const float* __restrict__ b_d) {
    __shared__ float4 sw0[Cc / 4], sw1[Cc / 4], sw2[Cc / 4];
    __shared__ float  sb[3];
    int node0 = blockIdx.x * 8;          // 8 warps per block, one node per warp
    int side  = (node0 >= Nn) ? 1 : 0;   // Nn % 8 == 0 -> block never straddles
    const float* w  = side ? w_d : w_i;
    const float* bb = side ? b_d : b_i;
    // transpose w[256][3] into three contiguous channel arrays
    for (int c = threadIdx.x; c < Cc; c += blockDim.x) {
        reinterpret_cast<float*>(sw0)[c] = w[c * 3 + 0];
        reinterpret_cast<float*>(sw1)[c] = w[c * 3 + 1];
        reinterpret_cast<float*>(sw2)[c] = w[c * 3 + 2];
    }
    if (threadIdx.x < 3) sb[threadIdx.x] = bb[threadIdx.x];
    __syncthreads();

    int warp = threadIdx.x >> 5;
    int lane = threadIdx.x & 31;
    int node = node0 + warp;
    const float* x = side ? (x_d + (long long)(node - Nn) * Cc)
                          : (x_i + (long long)node * Cc);
    float s0 = 0.f, s1 = 0.f, s2 = 0.f;
#pragma unroll
    for (int h = 0; h < 2; ++h) {
        int ci = lane + h * 32;                    // float4 index
        float4 xv = *reinterpret_cast<const float4*>(x + ci * 4);
        float4 w0 = sw0[ci], w1 = sw1[ci], w2 = sw2[ci];
        s0 += xv.x * w0.x + xv.y * w0.y + xv.z * w0.z + xv.w * w0.w;
        s1 += xv.x * w1.x + xv.y * w1.y + xv.z * w1.z + xv.w * w1.w;
        s2 += xv.x * w2.x + xv.y * w2.y + xv.z * w2.z + xv.w * w2.w;
    }
#pragma unroll
    for (int o = 16; o; o >>= 1) {
        s0 += __shfl_down_sync(0xFFFFFFFFu, s0, o);
        s1 += __shfl_down_sync(0xFFFFFFFFu, s1, o);
        s2 += __shfl_down_sync(0xFFFFFFFFu, s2, o);
    }
    if (lane == 0) {
        g_kv[node] = make_float2(s0 + sb[0], s2 + sb[2]);   // (k, v)
        g_q[node]  = s1 + sb[1];
    }
}

// ---- single fused edge pass: exp(logit) sums, no max-shift -----------------
// alpha = exp(l)/sum exp(l) is shift-invariant; |logit| <~ 50 keeps exp in
// fp32 range, so the segment-max pass is unnecessary.
__global__ void edge_kernel(const int* __restrict__ ei0, const int* __restrict__ ei1,
                            const int* __restrict__ ei2,
                            const float* __restrict__ krel_w, const float* __restrict__ krel_b,
                            const float* __restrict__ vrel_w, const float* __restrict__ vrel_b,
                            const float* __restrict__ p_rel) {
    int t = blockIdx.x >> 12;                                   // 0,1,2 (uniform per block)
    int i = ((blockIdx.x & 4095) << 8) | threadIdx.x;
    const int* ei = (t == 0) ? ei0 : ((t == 1) ? ei1 : ei2);
    int s = ei[i];
    int d = ei[Ee + i];
    int sbase = (t == 1) ? Nn : 0;
    int dbase = (t == 0) ? Nn : 0;
    int dg = dbase + d;
    float kw = krel_w[t], kb = krel_b[t];
    float vw = vrel_w[t], vb = vrel_b[t];
    float pr = p_rel[t];
    float2 kv = __ldg(&g_kv[sbase + s]);
    float  q  = __ldg(&g_q[dg]);
    float ke = kv.x * kw + kb;
    float ve = kv.y * vw + vb;
    float ex = __expf(q * ke * pr);
    atomicAdd(&g_dn[dg], make_float2(ex * ve, ex));
}

// ---- score + per-batch top-K selection -> pooling weights -----------------
__global__ void select_kernel(const float* __restrict__ w_out_i, const float* __restrict__ b_out_i,
                              const float* __restrict__ w_out_d, const float* __restrict__ b_out_d) {
    __shared__ unsigned skey[NPGv];
    __shared__ float    sval[NPGv];
    __shared__ int      scnt;
    int side = blockIdx.x >> 4;      // 0..1
    int b    = blockIdx.x & 15;      // 0..15
    int base = side * Nn + b * NPGv;
    float wo = side ? w_out_d[0] : w_out_i[0];
    float bo = side ? b_out_d[0] : b_out_i[0];

    for (int j = threadIdx.x; j < NPGv; j += blockDim.x) {
        float2 dn = g_dn[base + j];
        float a   = (dn.y > 0.f) ? (dn.x / dn.y) : 0.f;   // empty segment -> 0
        float z   = a * wo + bo;
        float sc  = 0.5f * z * (1.f + erff(z * 0.70710678118654752f));  // exact gelu
        sval[j] = sc;
        skey[j] = encf(sc);
    }
    __syncthreads();

    int lane = threadIdx.x & 31;
    auto count_ge = [&](unsigned key) -> int {
        if (threadIdx.x == 0) scnt = 0;
        __syncthreads();
        int c = 0;
        for (int j = threadIdx.x; j < NPGv; j += blockDim.x) c += (skey[j] >= key) ? 1 : 0;
#pragma unroll
        for (int o = 16; o; o >>= 1) c += __shfl_down_sync(0xFFFFFFFFu, c, o);
        if (lane == 0) atomicAdd(&scnt, c);
        __syncthreads();
        int r = scnt;
        __syncthreads();
        return r;
    };

    // largest thr with count(key >= thr) >= K (binary search on key space)
    unsigned lo = 0u, hi = 0xFFFFFFFFu;
    while (lo < hi) {
        unsigned mid = (unsigned)((((unsigned long long)lo + (unsigned long long)hi) + 1ull) >> 1);
        if (count_ge(mid) >= Kk) lo = mid; else hi = mid - 1u;
    }
    unsigned thr = lo;
    int cnt_gt = (thr == 0xFFFFFFFFu) ? 0 : count_ge(thr + 1u);
    int need_eq = Kk - cnt_gt;

    for (int j = threadIdx.x; j < NPGv; j += blockDim.x) {
        unsigned key = skey[j];
        bool sel = key > thr;
        if (key == thr) {
            // tie-break by smallest index, matching lax.top_k
            int rank = 0;
            for (int j2 = 0; j2 < j; ++j2) rank += (skey[j2] == thr) ? 1 : 0;
            sel = rank < need_eq;
        }
        g_wt[base + j] = sel ? tanhf(sval[j]) * (1.f / (float)Kk) : 0.f;
    }
}

// ---- pooling: weighted sum of selected rows -------------------------------
__global__ void pool_kernel(const float* __restrict__ x_i, const float* __restrict__ x_d,
                            float* __restrict__ out) {
    __shared__ float sw[NPGv / SPLIT];   // 512
    int part = blockIdx.x & (SPLIT - 1);
    int sb   = blockIdx.x >> 3;          // SPLIT == 8
    int side = sb >> 4;
    int b    = sb & 15;
    int c    = threadIdx.x;              // 256 threads = one column each
    const float* x = side ? x_d : x_i;
    const int rows_per = NPGv / SPLIT;
    int r0 = part * rows_per;
    int nodebase = side * Nn + b * NPGv + r0;
    long long rowbase = (long long)(b * NPGv + r0) * Cc;

    for (int r = threadIdx.x; r < rows_per; r += blockDim.x) sw[r] = g_wt[nodebase + r];
    __syncthreads();

    float acc = 0.f;
    for (int r = 0; r < rows_per; ++r) {
        float w = sw[r];
        if (w != 0.f) acc += w * x[rowbase + (long long)r * Cc + c];
    }
    atomicAdd(&out[b * (2 * Cc) + side * Cc + c], acc);
}

// ---- launch ----------------------------------------------------------------
extern "C" void kernel_launch(void* const* d_in, const int* in_sizes, int n_in,
                              void* d_out, int out_size) {
    const float* x_inst     = (const float*)d_in[0];
    const float* x_data     = (const float*)d_in[1];
    const float* w_kqv_inst = (const float*)d_in[2];
    const float* b_kqv_inst = (const float*)d_in[3];
    const float* w_kqv_data = (const float*)d_in[4];
    const float* b_kqv_data = (const float*)d_in[5];
    const float* w_out_inst = (const float*)d_in[6];
    const float* b_out_inst = (const float*)d_in[7];
    const float* w_out_data = (const float*)d_in[8];
    const float* b_out_data = (const float*)d_in[9];
    const float* krel_w     = (const float*)d_in[10];
    const float* krel_b     = (const float*)d_in[11];
    const float* vrel_w     = (const float*)d_in[12];
    const float* vrel_b     = (const float*)d_in[13];
    const float* p_rel      = (const float*)d_in[14];
    const int*   ei_i2d     = (const int*)d_in[15];
    const int*   ei_d2i     = (const int*)d_in[16];
    const int*   ei_i2i     = (const int*)d_in[17];
    float* out = (float*)d_out;

    init_kernel<<<(NT + 255) / 256, 256>>>(out);
    kqv_kernel<<<(2 * Nn) / 8, 256>>>(x_inst, x_data, w_kqv_inst, b_kqv_inst,
                                      w_kqv_data, b_kqv_data);
    edge_kernel<<<3 * (Ee / 256), 256>>>(ei_i2d, ei_d2i, ei_i2i, krel_w, krel_b,
                                         vrel_w, vrel_b, p_rel);
    select_kernel<<<2 * Bb, 512>>>(w_out_inst, b_out_inst, w_out_data, b_out_data);
    pool_kernel<<<2 * Bb * SPLIT, 256>>>(x_inst, x_data, out);
}

// round 3
// speedup vs baseline: 1.7438x; 1.2415x over previous
#include <cuda_runtime.h>
#include <math.h>

// Problem constants (fixed shapes)
namespace {
constexpr int Nn   = 65536;    // B*NPG nodes per side
constexpr int Cc   = 256;      // feature dim
constexpr int Ee   = 1048576;  // edges per edge set
constexpr int Bb   = 16;       // batch
constexpr int NPGv = 4096;     // nodes per graph
constexpr int Kk   = 1024;     // top-k
constexpr int NT   = 131072;   // 2*N
constexpr int SPLIT = 8;       // pooling row splits per (side,batch)
}

// Scratch (device globals: no allocation allowed)
__device__ float2 g_kv[NT];    // (k, v) packed -> one gather sector
__device__ float  g_q[NT];
__device__ float2 g_dn[NT];    // (num, den) packed -> one vector atomic
__device__ float  g_wt[NT];    // pooling weight per node (tanh(score)/K or 0)

// ---- float <-> order-preserving uint ------------------------------------
__device__ __forceinline__ unsigned encf(float f) {
    unsigned u = __float_as_uint(f);
    return (u & 0x80000000u) ? ~u : (u | 0x80000000u);
}

// ---- init: zero accumulators + output -----------------------------------
__global__ void init_kernel(float* __restrict__ out) {
    int i = blockIdx.x * blockDim.x + threadIdx.x;
    if (i < NT) g_dn[i] = make_float2(0.f, 0.f);
    if (i < Bb * 2 * Cc) out[i] = 0.f;
}

// ---- kqv: per-node 3 dot products (warp per node), conflict-free smem ----
__global__ void kqv_kernel(const float* __restrict__ x_i, const float* __restrict__ x_d,
                           const float* __restrict__ w_i, const float* __restrict__ b_i,
                           const float* __restrict__ w_d, const float* __restrict__ b_d) {
    __shared__ float4 sw0[Cc / 4], sw1[Cc / 4], sw2[Cc / 4];
    __shared__ float  sb[3];
    int node0 = blockIdx.x * 8;          // 8 warps per block, one node per warp
    int side  = (node0 >= Nn) ? 1 : 0;   // Nn % 8 == 0 -> block never straddles
    const float* w  = side ? w_d : w_i;
    const float* bb = side ? b_d : b_i;
    for (int c = threadIdx.x; c < Cc; c += blockDim.x) {
        reinterpret_cast<float*>(sw0)[c] = w[c * 3 + 0];
        reinterpret_cast<float*>(sw1)[c] = w[c * 3 + 1];
        reinterpret_cast<float*>(sw2)[c] = w[c * 3 + 2];
    }
    if (threadIdx.x < 3) sb[threadIdx.x] = bb[threadIdx.x];
    __syncthreads();

    int warp = threadIdx.x >> 5;
    int lane = threadIdx.x & 31;
    int node = node0 + warp;
    const float* x = side ? (x_d + (long long)(node - Nn) * Cc)
                          : (x_i + (long long)node * Cc);
    float s0 = 0.f, s1 = 0.f, s2 = 0.f;
#pragma unroll
    for (int h = 0; h < 2; ++h) {
        int ci = lane + h * 32;                    // float4 index
        float4 xv = *reinterpret_cast<const float4*>(x + ci * 4);
        float4 w0 = sw0[ci], w1 = sw1[ci], w2 = sw2[ci];
        s0 += xv.x * w0.x + xv.y * w0.y + xv.z * w0.z + xv.w * w0.w;
        s1 += xv.x * w1.x + xv.y * w1.y + xv.z * w1.z + xv.w * w1.w;
        s2 += xv.x * w2.x + xv.y * w2.y + xv.z * w2.z + xv.w * w2.w;
    }
#pragma unroll
    for (int o = 16; o; o >>= 1) {
        s0 += __shfl_down_sync(0xFFFFFFFFu, s0, o);
        s1 += __shfl_down_sync(0xFFFFFFFFu, s1, o);
        s2 += __shfl_down_sync(0xFFFFFFFFu, s2, o);
    }
    if (lane == 0) {
        g_kv[node] = make_float2(s0 + sb[0], s2 + sb[2]);   // (k, v)
        g_q[node]  = s1 + sb[1];
    }
}

// ---- single fused edge pass: exp(logit) sums, no max-shift -----------------
__global__ void edge_kernel(const int* __restrict__ ei0, const int* __restrict__ ei1,
                            const int* __restrict__ ei2,
                            const float* __restrict__ krel_w, const float* __restrict__ krel_b,
                            const float* __restrict__ vrel_w, const float* __restrict__ vrel_b,
                            const float* __restrict__ p_rel) {
    int t = blockIdx.x >> 12;                                   // 0,1,2 (uniform per block)
    int i = ((blockIdx.x & 4095) << 8) | threadIdx.x;
    const int* ei = (t == 0) ? ei0 : ((t == 1) ? ei1 : ei2);
    int s = ei[i];
    int d = ei[Ee + i];
    int sbase = (t == 1) ? Nn : 0;
    int dbase = (t == 0) ? Nn : 0;
    int dg = dbase + d;
    float kw = krel_w[t], kb = krel_b[t];
    float vw = vrel_w[t], vb = vrel_b[t];
    float pr = p_rel[t];
    float2 kv = __ldg(&g_kv[sbase + s]);
    float  q  = __ldg(&g_q[dg]);
    float ke = kv.x * kw + kb;
    float ve = kv.y * vw + vb;
    float ex = __expf(q * ke * pr);
    atomicAdd(&g_dn[dg], make_float2(ex * ve, ex));
}

// ---- score + per-batch top-K (radix select) -> pooling weights -------------
__global__ void select_kernel(const float* __restrict__ w_out_i, const float* __restrict__ b_out_i,
                              const float* __restrict__ w_out_d, const float* __restrict__ b_out_d) {
    constexpr int T = 512;
    constexpr int CHUNK = NPGv / T;   // 8
    __shared__ unsigned skey[NPGv];
    __shared__ float    sval[NPGv];
    __shared__ int      hist[256];
    __shared__ int      s_sel, s_rem;
    __shared__ int      warp_sums[16];
    int tid  = threadIdx.x;
    int side = blockIdx.x >> 4;      // 0..1
    int b    = blockIdx.x & 15;      // 0..15
    int base = side * Nn + b * NPGv;
    float wo = side ? w_out_d[0] : w_out_i[0];
    float bo = side ? b_out_d[0] : b_out_i[0];

    for (int j = tid; j < NPGv; j += T) {
        float2 dn = g_dn[base + j];
        float a   = (dn.y > 0.f) ? (dn.x / dn.y) : 0.f;   // empty segment -> 0
        float z   = a * wo + bo;
        float sc  = 0.5f * z * (1.f + erff(z * 0.70710678118654752f));  // exact gelu
        sval[j] = sc;
        skey[j] = encf(sc);
    }

    // 4-pass radix select for the Kk-th largest key
    unsigned prefix = 0u;
    int remaining = Kk;
#pragma unroll
    for (int shift = 24; shift >= 0; shift -= 8) {
        unsigned umask = (shift == 24) ? 0u : (0xFFFFFFFFu << (shift + 8));
        __syncthreads();
        if (tid < 256) hist[tid] = 0;
        __syncthreads();
        for (int j = tid; j < NPGv; j += T) {
            unsigned key = skey[j];
            if ((key & umask) == (prefix & umask))
                atomicAdd(&hist[(key >> shift) & 255], 1);
        }
        __syncthreads();
        // in-place suffix-sum: hist[b] = count of candidates with digit >= b
        for (int off = 1; off < 256; off <<= 1) {
            int v = 0;
            if (tid < 256 && tid + off < 256) v = hist[tid + off];
            __syncthreads();
            if (tid < 256) hist[tid] += v;
            __syncthreads();
        }
        if (tid < 256) {
            int above = (tid == 255) ? 0 : hist[tid + 1];
            if (hist[tid] >= remaining && above < remaining) {
                s_sel = tid;
                s_rem = remaining - above;
            }
        }
        __syncthreads();
        prefix |= ((unsigned)s_sel) << shift;
        remaining = s_rem;
    }
    unsigned thr = prefix;           // Kk-th largest key
    int need_eq = remaining;         // #ties at thr to keep (lowest index first)

    // blocked tie-rank: thread owns 8 contiguous indices; block-wide excl scan
    __syncthreads();
    int j0 = tid * CHUNK;
    int myties = 0;
#pragma unroll
    for (int u = 0; u < CHUNK; ++u) myties += (skey[j0 + u] == thr) ? 1 : 0;
    int lane = tid & 31, warp = tid >> 5;
    int incl = myties;
#pragma unroll
    for (int off = 1; off < 32; off <<= 1) {
        int v = __shfl_up_sync(0xFFFFFFFFu, incl, off);
        if (lane >= off) incl += v;
    }
    if (lane == 31) warp_sums[warp] = incl;
    __syncthreads();
    if (tid < 16) {
        int v = warp_sums[tid];
#pragma unroll
        for (int off = 1; off < 16; off <<= 1) {
            int t2 = __shfl_up_sync(0x0000FFFFu, v, off);
            if (tid >= off) v += t2;
        }
        warp_sums[tid] = v;
    }
    __syncthreads();
    int r = incl - myties + (warp ? warp_sums[warp - 1] : 0);

#pragma unroll
    for (int u = 0; u < CHUNK; ++u) {
        int j = j0 + u;
        unsigned key = skey[j];
        bool sel = key > thr;
        if (key == thr) { sel = (r < need_eq); ++r; }
        g_wt[base + j] = sel ? tanhf(sval[j]) * (1.f / (float)Kk) : 0.f;
    }
}

// ---- pooling: weighted sum of selected rows -------------------------------
__global__ void pool_kernel(const float* __restrict__ x_i, const float* __restrict__ x_d,
                            float* __restrict__ out) {
    __shared__ float sw[NPGv / SPLIT];   // 512
    int part = blockIdx.x & (SPLIT - 1);
    int sb   = blockIdx.x >> 3;          // SPLIT == 8
    int side = sb >> 4;
    int b    = sb & 15;
    int c    = threadIdx.x;              // 256 threads = one column each
    const float* x = side ? x_d : x_i;
    const int rows_per = NPGv / SPLIT;
    int r0 = part * rows_per;
    int nodebase = side * Nn + b * NPGv + r0;
    long long rowbase = (long long)(b * NPGv + r0) * Cc;

    for (int r = threadIdx.x; r < rows_per; r += blockDim.x) sw[r] = g_wt[nodebase + r];
    __syncthreads();

    float acc = 0.f;
    for (int r = 0; r < rows_per; ++r) {
        float w = sw[r];
        if (w != 0.f) acc += w * x[rowbase + (long long)r * Cc + c];
    }
    atomicAdd(&out[b * (2 * Cc) + side * Cc + c], acc);
}

// ---- launch ----------------------------------------------------------------
extern "C" void kernel_launch(void* const* d_in, const int* in_sizes, int n_in,
                              void* d_out, int out_size) {
    const float* x_inst     = (const float*)d_in[0];
    const float* x_data     = (const float*)d_in[1];
    const float* w_kqv_inst = (const float*)d_in[2];
    const float* b_kqv_inst = (const float*)d_in[3];
    const float* w_kqv_data = (const float*)d_in[4];
    const float* b_kqv_data = (const float*)d_in[5];
    const float* w_out_inst = (const float*)d_in[6];
    const float* b_out_inst = (const float*)d_in[7];
    const float* w_out_data = (const float*)d_in[8];
    const float* b_out_data = (const float*)d_in[9];
    const float* krel_w     = (const float*)d_in[10];
    const float* krel_b     = (const float*)d_in[11];
    const float* vrel_w     = (const float*)d_in[12];
    const float* vrel_b     = (const float*)d_in[13];
    const float* p_rel      = (const float*)d_in[14];
    const int*   ei_i2d     = (const int*)d_in[15];
    const int*   ei_d2i     = (const int*)d_in[16];
    const int*   ei_i2i     = (const int*)d_in[17];
    float* out = (float*)d_out;

    init_kernel<<<(NT + 255) / 256, 256>>>(out);
    kqv_kernel<<<(2 * Nn) / 8, 256>>>(x_inst, x_data, w_kqv_inst, b_kqv_inst,
                                      w_kqv_data, b_kqv_data);
    edge_kernel<<<3 * (Ee / 256), 256>>>(ei_i2d, ei_d2i, ei_i2i, krel_w, krel_b,
                                         vrel_w, vrel_b, p_rel);
    select_kernel<<<2 * Bb, 512>>>(w_out_inst, b_out_inst, w_out_data, b_out_data);
    pool_kernel<<<2 * Bb * SPLIT, 256>>>(x_inst, x_data, out);
}

// round 4
// speedup vs baseline: 2.1289x; 1.2209x over previous
#include <cuda_runtime.h>
#include <math.h>

// Problem constants (fixed shapes)
namespace {
constexpr int Nn   = 65536;    // B*NPG nodes per side
constexpr int Cc   = 256;      // feature dim
constexpr int Ee   = 1048576;  // edges per edge set
constexpr int Bb   = 16;       // batch
constexpr int NPGv = 4096;     // nodes per graph
constexpr int Kk   = 1024;     // top-k
constexpr int NT   = 131072;   // 2*N
constexpr int SPLIT = 8;       // pooling row splits per (side,batch)
}

// Scratch (device globals: no allocation allowed)
__device__ float2 g_kv[NT];    // (k, v) packed -> one gather sector
__device__ float4 g_dnq[NT];   // (num, den, q, pad): atomic+q-gather share a sector
__device__ float  g_wt[NT];    // pooling weight per node (tanh(score)/K or 0)

// ---- float <-> order-preserving uint ------------------------------------
__device__ __forceinline__ unsigned encf(float f) {
    unsigned u = __float_as_uint(f);
    return (u & 0x80000000u) ? ~u : (u | 0x80000000u);
}

// ---- init: zero accumulators + output -----------------------------------
__global__ void init_kernel(float* __restrict__ out) {
    int i = blockIdx.x * blockDim.x + threadIdx.x;
    if (i < NT) *reinterpret_cast<float2*>(&g_dnq[i]) = make_float2(0.f, 0.f);
    if (i < Bb * 2 * Cc) out[i] = 0.f;
}

// ---- kqv: per-node 3 dot products (warp per node), conflict-free smem ----
__global__ void kqv_kernel(const float* __restrict__ x_i, const float* __restrict__ x_d,
                           const float* __restrict__ w_i, const float* __restrict__ b_i,
                           const float* __restrict__ w_d, const float* __restrict__ b_d) {
    __shared__ float4 sw0[Cc / 4], sw1[Cc / 4], sw2[Cc / 4];
    __shared__ float  sb[3];
    int node0 = blockIdx.x * 8;          // 8 warps per block, one node per warp
    int side  = (node0 >= Nn) ? 1 : 0;   // Nn % 8 == 0 -> block never straddles
    const float* w  = side ? w_d : w_i;
    const float* bb = side ? b_d : b_i;
    for (int c = threadIdx.x; c < Cc; c += blockDim.x) {
        reinterpret_cast<float*>(sw0)[c] = w[c * 3 + 0];
        reinterpret_cast<float*>(sw1)[c] = w[c * 3 + 1];
        reinterpret_cast<float*>(sw2)[c] = w[c * 3 + 2];
    }
    if (threadIdx.x < 3) sb[threadIdx.x] = bb[threadIdx.x];
    __syncthreads();

    int warp = threadIdx.x >> 5;
    int lane = threadIdx.x & 31;
    int node = node0 + warp;
    const float* x = side ? (x_d + (long long)(node - Nn) * Cc)
                          : (x_i + (long long)node * Cc);
    float s0 = 0.f, s1 = 0.f, s2 = 0.f;
#pragma unroll
    for (int h = 0; h < 2; ++h) {
        int ci = lane + h * 32;                    // float4 index
        float4 xv = *reinterpret_cast<const float4*>(x + ci * 4);
        float4 w0 = sw0[ci], w1 = sw1[ci], w2 = sw2[ci];
        s0 += xv.x * w0.x + xv.y * w0.y + xv.z * w0.z + xv.w * w0.w;
        s1 += xv.x * w1.x + xv.y * w1.y + xv.z * w1.z + xv.w * w1.w;
        s2 += xv.x * w2.x + xv.y * w2.y + xv.z * w2.z + xv.w * w2.w;
    }
#pragma unroll
    for (int o = 16; o; o >>= 1) {
        s0 += __shfl_down_sync(0xFFFFFFFFu, s0, o);
        s1 += __shfl_down_sync(0xFFFFFFFFu, s1, o);
        s2 += __shfl_down_sync(0xFFFFFFFFu, s2, o);
    }
    if (lane == 0) {
        g_kv[node]   = make_float2(s0 + sb[0], s2 + sb[2]);   // (k, v)
        g_dnq[node].z = s1 + sb[1];                            // q
    }
}

// ---- single fused edge pass: exp(logit) sums, no max-shift -----------------
__global__ void edge_kernel(const int* __restrict__ ei0, const int* __restrict__ ei1,
                            const int* __restrict__ ei2,
                            const float* __restrict__ krel_w, const float* __restrict__ krel_b,
                            const float* __restrict__ vrel_w, const float* __restrict__ vrel_b,
                            const float* __restrict__ p_rel) {
    int t = blockIdx.x >> 12;                                   // 0,1,2 (uniform per block)
    int i = ((blockIdx.x & 4095) << 8) | threadIdx.x;
    const int* ei = (t == 0) ? ei0 : ((t == 1) ? ei1 : ei2);
    int s = ei[i];
    int d = ei[Ee + i];
    int sbase = (t == 1) ? Nn : 0;
    int dbase = (t == 0) ? Nn : 0;
    int dg = dbase + d;
    float kw = krel_w[t], kb = krel_b[t];
    float vw = vrel_w[t], vb = vrel_b[t];
    float pr = p_rel[t];
    float2 kv = __ldg(&g_kv[sbase + s]);
    float  q  = __ldg(&g_dnq[dg].z);                 // same sector as atomic target
    float ke = kv.x * kw + kb;
    float ve = kv.y * vw + vb;
    float ex = __expf(q * ke * pr);
    atomicAdd(reinterpret_cast<float2*>(&g_dnq[dg]), make_float2(ex * ve, ex));
}

// ---- score + per-batch top-K (radix select, warp-scan) -> pooling weights --
__global__ void select_kernel(const float* __restrict__ w_out_i, const float* __restrict__ b_out_i,
                              const float* __restrict__ w_out_d, const float* __restrict__ b_out_d) {
    constexpr int T = 1024;
    constexpr int CHUNK = NPGv / T;   // 4
    __shared__ unsigned skey[NPGv];
    __shared__ float    sval[NPGv];
    __shared__ int      hist[256];
    __shared__ int      s_sel, s_rem;
    __shared__ int      warp_sums[32];
    int tid  = threadIdx.x;
    int side = blockIdx.x >> 4;      // 0..1
    int b    = blockIdx.x & 15;      // 0..15
    int base = side * Nn + b * NPGv;
    float wo = side ? w_out_d[0] : w_out_i[0];
    float bo = side ? b_out_d[0] : b_out_i[0];

    for (int j = tid; j < NPGv; j += T) {
        float4 dn = g_dnq[base + j];
        float a   = (dn.y > 0.f) ? (dn.x / dn.y) : 0.f;   // empty segment -> 0
        float z   = a * wo + bo;
        float sc  = 0.5f * z * (1.f + erff(z * 0.70710678118654752f));  // exact gelu
        sval[j] = sc;
        skey[j] = encf(sc);
    }
    if (tid == 0) s_rem = Kk;

    // 4-pass radix select for the Kk-th largest key
    unsigned prefix = 0u;
#pragma unroll
    for (int shift = 24; shift >= 0; shift -= 8) {
        unsigned umask = (shift == 24) ? 0u : (0xFFFFFFFFu << (shift + 8));
        __syncthreads();
        if (tid < 256) hist[tid] = 0;
        __syncthreads();
#pragma unroll
        for (int u = 0; u < CHUNK; ++u) {
            unsigned key = skey[tid + u * T];
            if ((key & umask) == (prefix & umask))
                atomicAdd(&hist[(key >> shift) & 255], 1);
        }
        __syncthreads();
        if (tid < 32) {
            int rem = s_rem;
            int h[8], sfx[8];
            int bin0 = tid * 8;
#pragma unroll
            for (int j = 0; j < 8; ++j) h[j] = hist[bin0 + j];
            sfx[7] = h[7];
#pragma unroll
            for (int j = 6; j >= 0; --j) sfx[j] = h[j] + sfx[j + 1];
            int tot = sfx[0];
            // inclusive suffix across lanes
            int suf = tot;
#pragma unroll
            for (int off = 1; off < 32; off <<= 1) {
                int v = __shfl_down_sync(0xFFFFFFFFu, suf, off);
                if (tid + off < 32) suf += v;
            }
            int above_lane = suf - tot;   // sum of bins >= (tid+1)*8
#pragma unroll
            for (int j = 0; j < 8; ++j) {
                int cnt_ge    = sfx[j] + above_lane;
                int cnt_above = (j == 7) ? above_lane : (sfx[j + 1] + above_lane);
                if (cnt_ge >= rem && cnt_above < rem) {
                    s_sel = bin0 + j;
                    s_rem = rem - cnt_above;
                }
            }
        }
        __syncthreads();
        prefix |= ((unsigned)s_sel) << shift;
    }
    unsigned thr = prefix;           // Kk-th largest key
    int need_eq = s_rem;             // #ties at thr to keep (lowest index first)

    // blocked tie-rank: thread owns CHUNK contiguous indices; block excl scan
    int j0 = tid * CHUNK;
    int myties = 0;
#pragma unroll
    for (int u = 0; u < CHUNK; ++u) myties += (skey[j0 + u] == thr) ? 1 : 0;
    int lane = tid & 31, warp = tid >> 5;
    int incl = myties;
#pragma unroll
    for (int off = 1; off < 32; off <<= 1) {
        int v = __shfl_up_sync(0xFFFFFFFFu, incl, off);
        if (lane >= off) incl += v;
    }
    if (lane == 31) warp_sums[warp] = incl;
    __syncthreads();
    if (tid < 32) {
        int v = warp_sums[tid];
#pragma unroll
        for (int off = 1; off < 32; off <<= 1) {
            int t2 = __shfl_up_sync(0xFFFFFFFFu, v, off);
            if (tid >= off) v += t2;
        }
        warp_sums[tid] = v;
    }
    __syncthreads();
    int r = incl - myties + (warp ? warp_sums[warp - 1] : 0);

#pragma unroll
    for (int u = 0; u < CHUNK; ++u) {
        int j = j0 + u;
        unsigned key = skey[j];
        bool sel = key > thr;
        if (key == thr) { sel = (r < need_eq); ++r; }
        g_wt[base + j] = sel ? tanhf(sval[j]) * (1.f / (float)Kk) : 0.f;
    }
}

// ---- pooling: weighted sum of selected rows (float4, 4 row-groups) ---------
__global__ void pool_kernel(const float* __restrict__ x_i, const float* __restrict__ x_d,
                            float* __restrict__ out) {
    __shared__ float sw[NPGv / SPLIT];   // 512
    int part = blockIdx.x & (SPLIT - 1);
    int sb   = blockIdx.x >> 3;          // SPLIT == 8
    int side = sb >> 4;
    int b    = sb & 15;
    const float* x = side ? x_d : x_i;
    const int rows_per = NPGv / SPLIT;   // 512
    int r0 = part * rows_per;
    int nodebase = side * Nn + b * NPGv + r0;
    long long rowbase = (long long)(b * NPGv + r0) * Cc;

    for (int r = threadIdx.x; r < rows_per; r += blockDim.x) sw[r] = g_wt[nodebase + r];
    __syncthreads();

    int cg = threadIdx.x & 63;           // column group: cols cg*4..cg*4+3
    int rg = threadIdx.x >> 6;           // row group 0..3
    float4 acc = make_float4(0.f, 0.f, 0.f, 0.f);
    for (int r = rg; r < rows_per; r += 4) {
        float w = sw[r];
        if (w != 0.f) {
            float4 xv = *reinterpret_cast<const float4*>(x + rowbase + (long long)r * Cc + cg * 4);
            acc.x += w * xv.x; acc.y += w * xv.y;
            acc.z += w * xv.z; acc.w += w * xv.w;
        }
    }
    float* o = &out[b * (2 * Cc) + side * Cc + cg * 4];
    atomicAdd(reinterpret_cast<float2*>(o),     make_float2(acc.x, acc.y));
    atomicAdd(reinterpret_cast<float2*>(o + 2), make_float2(acc.z, acc.w));
}

// ---- launch ----------------------------------------------------------------
extern "C" void kernel_launch(void* const* d_in, const int* in_sizes, int n_in,
                              void* d_out, int out_size) {
    const float* x_inst     = (const float*)d_in[0];
    const float* x_data     = (const float*)d_in[1];
    const float* w_kqv_inst = (const float*)d_in[2];
    const float* b_kqv_inst = (const float*)d_in[3];
    const float* w_kqv_data = (const float*)d_in[4];
    const float* b_kqv_data = (const float*)d_in[5];
    const float* w_out_inst = (const float*)d_in[6];
    const float* b_out_inst = (const float*)d_in[7];
    const float* w_out_data = (const float*)d_in[8];
    const float* b_out_data = (const float*)d_in[9];
    const float* krel_w     = (const float*)d_in[10];
    const float* krel_b     = (const float*)d_in[11];
    const float* vrel_w     = (const float*)d_in[12];
    const float* vrel_b     = (const float*)d_in[13];
    const float* p_rel      = (const float*)d_in[14];
    const int*   ei_i2d     = (const int*)d_in[15];
    const int*   ei_d2i     = (const int*)d_in[16];
    const int*   ei_i2i     = (const int*)d_in[17];
    float* out = (float*)d_out;

    init_kernel<<<(NT + 255) / 256, 256>>>(out);
    kqv_kernel<<<(2 * Nn) / 8, 256>>>(x_inst, x_data, w_kqv_inst, b_kqv_inst,
                                      w_kqv_data, b_kqv_data);
    edge_kernel<<<3 * (Ee / 256), 256>>>(ei_i2d, ei_d2i, ei_i2i, krel_w, krel_b,
                                         vrel_w, vrel_b, p_rel);
    select_kernel<<<2 * Bb, 1024>>>(w_out_inst, b_out_inst, w_out_data, b_out_data);
    pool_kernel<<<2 * Bb * SPLIT, 256>>>(x_inst, x_data, out);
}

// round 5
// speedup vs baseline: 2.2451x; 1.0546x over previous
#include <cuda_runtime.h>
#include <math.h>

// Problem constants (fixed shapes)
namespace {
constexpr int Nn   = 65536;    // B*NPG nodes per side
constexpr int Cc   = 256;      // feature dim
constexpr int Ee   = 1048576;  // edges per edge set
constexpr int Bb   = 16;       // batch
constexpr int NPGv = 4096;     // nodes per graph
constexpr int Kk   = 1024;     // top-k
constexpr int NT   = 131072;   // 2*N
constexpr int SPLIT = 8;       // pooling row splits per (side,batch)
}

// Scratch (device globals: no allocation allowed)
__device__ float2 g_kv[NT];    // (k, v) packed -> one gather sector
__device__ float  g_q[NT];     // compact q table: per-type dst slice ~256KB -> L1-friendly
__device__ float2 g_dn[NT];    // (num, den) atomic accumulators
__device__ float  g_wt[NT];    // pooling weight per node (tanh(score)/K or 0)

// ---- float <-> order-preserving uint ------------------------------------
__device__ __forceinline__ unsigned encf(float f) {
    unsigned u = __float_as_uint(f);
    return (u & 0x80000000u) ? ~u : (u | 0x80000000u);
}

// ---- kqv: per-node 3 dot products (warp per node), conflict-free smem ----
// Also zeroes g_dn (runs before edge_kernel).
__global__ void kqv_kernel(const float* __restrict__ x_i, const float* __restrict__ x_d,
                           const float* __restrict__ w_i, const float* __restrict__ b_i,
                           const float* __restrict__ w_d, const float* __restrict__ b_d) {
    __shared__ float4 sw0[Cc / 4], sw1[Cc / 4], sw2[Cc / 4];
    __shared__ float  sb[3];
    int node0 = blockIdx.x * 8;          // 8 warps per block, one node per warp
    int side  = (node0 >= Nn) ? 1 : 0;   // Nn % 8 == 0 -> block never straddles
    const float* w  = side ? w_d : w_i;
    const float* bb = side ? b_d : b_i;
    for (int c = threadIdx.x; c < Cc; c += blockDim.x) {
        reinterpret_cast<float*>(sw0)[c] = w[c * 3 + 0];
        reinterpret_cast<float*>(sw1)[c] = w[c * 3 + 1];
        reinterpret_cast<float*>(sw2)[c] = w[c * 3 + 2];
    }
    if (threadIdx.x < 3) sb[threadIdx.x] = bb[threadIdx.x];
    __syncthreads();

    int warp = threadIdx.x >> 5;
    int lane = threadIdx.x & 31;
    int node = node0 + warp;
    const float* x = side ? (x_d + (long long)(node - Nn) * Cc)
                          : (x_i + (long long)node * Cc);
    float s0 = 0.f, s1 = 0.f, s2 = 0.f;
#pragma unroll
    for (int h = 0; h < 2; ++h) {
        int ci = lane + h * 32;                    // float4 index
        float4 xv = *reinterpret_cast<const float4*>(x + ci * 4);
        float4 w0 = sw0[ci], w1 = sw1[ci], w2 = sw2[ci];
        s0 += xv.x * w0.x + xv.y * w0.y + xv.z * w0.z + xv.w * w0.w;
        s1 += xv.x * w1.x + xv.y * w1.y + xv.z * w1.z + xv.w * w1.w;
        s2 += xv.x * w2.x + xv.y * w2.y + xv.z * w2.z + xv.w * w2.w;
    }
#pragma unroll
    for (int o = 16; o; o >>= 1) {
        s0 += __shfl_down_sync(0xFFFFFFFFu, s0, o);
        s1 += __shfl_down_sync(0xFFFFFFFFu, s1, o);
        s2 += __shfl_down_sync(0xFFFFFFFFu, s2, o);
    }
    if (lane == 0) {
        g_kv[node] = make_float2(s0 + sb[0], s2 + sb[2]);   // (k, v)
        g_q[node]  = s1 + sb[1];
        g_dn[node] = make_float2(0.f, 0.f);
    }
}

// ---- single fused edge pass: exp(logit) sums, no max-shift -----------------
// 2 edges per thread via int2 index loads.
__global__ void edge_kernel(const int* __restrict__ ei0, const int* __restrict__ ei1,
                            const int* __restrict__ ei2,
                            const float* __restrict__ krel_w, const float* __restrict__ krel_b,
                            const float* __restrict__ vrel_w, const float* __restrict__ vrel_b,
                            const float* __restrict__ p_rel) {
    int t  = blockIdx.x >> 11;                                 // 0,1,2 (uniform per block)
    int gi = ((blockIdx.x & 2047) << 8) | threadIdx.x;         // int2 index, 0..Ee/2-1
    const int* ei = (t == 0) ? ei0 : ((t == 1) ? ei1 : ei2);
    int2 ss = __ldg(reinterpret_cast<const int2*>(ei) + gi);
    int2 dd = __ldg(reinterpret_cast<const int2*>(ei + Ee) + gi);
    int sbase = (t == 1) ? Nn : 0;
    int dbase = (t == 0) ? Nn : 0;
    float kw = krel_w[t], kb = krel_b[t];
    float vw = vrel_w[t], vb = vrel_b[t];
    float pr = p_rel[t];

    int dg0 = dbase + dd.x, dg1 = dbase + dd.y;
    float2 kv0 = __ldg(&g_kv[sbase + ss.x]);
    float2 kv1 = __ldg(&g_kv[sbase + ss.y]);
    float  q0  = __ldg(&g_q[dg0]);
    float  q1  = __ldg(&g_q[dg1]);

    float ex0 = __expf(q0 * (kv0.x * kw + kb) * pr);
    float ex1 = __expf(q1 * (kv1.x * kw + kb) * pr);
    float ve0 = kv0.y * vw + vb;
    float ve1 = kv1.y * vw + vb;
    atomicAdd(&g_dn[dg0], make_float2(ex0 * ve0, ex0));
    atomicAdd(&g_dn[dg1], make_float2(ex1 * ve1, ex1));
}

// ---- score + per-batch top-K (radix select, warp-aggregated hist) ----------
// Also zeroes this block's 256-float slice of out (runs before pool_kernel).
__global__ void select_kernel(const float* __restrict__ w_out_i, const float* __restrict__ b_out_i,
                              const float* __restrict__ w_out_d, const float* __restrict__ b_out_d,
                              float* __restrict__ out) {
    constexpr int T = 1024;
    constexpr int CHUNK = NPGv / T;   // 4
    __shared__ unsigned skey[NPGv];
    __shared__ float    sval[NPGv];
    __shared__ int      hist[256];
    __shared__ int      s_sel, s_rem;
    __shared__ int      warp_sums[32];
    int tid  = threadIdx.x;
    int side = blockIdx.x >> 4;      // 0..1
    int b    = blockIdx.x & 15;      // 0..15
    int base = side * Nn + b * NPGv;
    float wo = side ? w_out_d[0] : w_out_i[0];
    float bo = side ? b_out_d[0] : b_out_i[0];

    if (tid < Cc) out[b * (2 * Cc) + side * Cc + tid] = 0.f;   // zero own out slice

    for (int j = tid; j < NPGv; j += T) {
        float2 dn = g_dn[base + j];
        float a   = (dn.y > 0.f) ? (dn.x / dn.y) : 0.f;   // empty segment -> 0
        float z   = a * wo + bo;
        float sc  = 0.5f * z * (1.f + erff(z * 0.70710678118654752f));  // exact gelu
        sval[j] = sc;
        skey[j] = encf(sc);
    }
    if (tid == 0) s_rem = Kk;

    // 4-pass radix select for the Kk-th largest key
    unsigned prefix = 0u;
#pragma unroll
    for (int shift = 24; shift >= 0; shift -= 8) {
        unsigned umask = (shift == 24) ? 0u : (0xFFFFFFFFu << (shift + 8));
        __syncthreads();
        if (tid < 256) hist[tid] = 0;
        __syncthreads();
#pragma unroll
        for (int u = 0; u < CHUNK; ++u) {
            unsigned key = skey[tid + u * T];
            bool act = (key & umask) == (prefix & umask);
            if (act) {
                unsigned bin   = (key >> shift) & 255u;
                unsigned peers = __match_any_sync(__activemask(), bin);
                int leader = __ffs(peers) - 1;
                if ((tid & 31) == leader) atomicAdd(&hist[bin], __popc(peers));
            }
        }
        __syncthreads();
        if (tid < 32) {
            int rem = s_rem;
            int h[8], sfx[8];
            int bin0 = tid * 8;
#pragma unroll
            for (int j = 0; j < 8; ++j) h[j] = hist[bin0 + j];
            sfx[7] = h[7];
#pragma unroll
            for (int j = 6; j >= 0; --j) sfx[j] = h[j] + sfx[j + 1];
            int tot = sfx[0];
            // inclusive suffix across lanes
            int suf = tot;
#pragma unroll
            for (int off = 1; off < 32; off <<= 1) {
                int v = __shfl_down_sync(0xFFFFFFFFu, suf, off);
                if (tid + off < 32) suf += v;
            }
            int above_lane = suf - tot;   // sum of bins >= (tid+1)*8
#pragma unroll
            for (int j = 0; j < 8; ++j) {
                int cnt_ge    = sfx[j] + above_lane;
                int cnt_above = (j == 7) ? above_lane : (sfx[j + 1] + above_lane);
                if (cnt_ge >= rem && cnt_above < rem) {
                    s_sel = bin0 + j;
                    s_rem = rem - cnt_above;
                }
            }
        }
        __syncthreads();
        prefix |= ((unsigned)s_sel) << shift;
    }
    unsigned thr = prefix;           // Kk-th largest key
    int need_eq = s_rem;             // #ties at thr to keep (lowest index first)

    // blocked tie-rank: thread owns CHUNK contiguous indices; block excl scan
    int j0 = tid * CHUNK;
    int myties = 0;
#pragma unroll
    for (int u = 0; u < CHUNK; ++u) myties += (skey[j0 + u] == thr) ? 1 : 0;
    int lane = tid & 31, warp = tid >> 5;
    int incl = myties;
#pragma unroll
    for (int off = 1; off < 32; off <<= 1) {
        int v = __shfl_up_sync(0xFFFFFFFFu, incl, off);
        if (lane >= off) incl += v;
    }
    if (lane == 31) warp_sums[warp] = incl;
    __syncthreads();
    if (tid < 32) {
        int v = warp_sums[tid];
#pragma unroll
        for (int off = 1; off < 32; off <<= 1) {
            int t2 = __shfl_up_sync(0xFFFFFFFFu, v, off);
            if (tid >= off) v += t2;
        }
        warp_sums[tid] = v;
    }
    __syncthreads();
    int r = incl - myties + (warp ? warp_sums[warp - 1] : 0);

#pragma unroll
    for (int u = 0; u < CHUNK; ++u) {
        int j = j0 + u;
        unsigned key = skey[j];
        bool sel = key > thr;
        if (key == thr) { sel = (r < need_eq); ++r; }
        g_wt[base + j] = sel ? tanhf(sval[j]) * (1.f / (float)Kk) : 0.f;
    }
}

// ---- pooling: weighted sum of selected rows (float4, 4 row-groups) ---------
__global__ void pool_kernel(const float* __restrict__ x_i, const float* __restrict__ x_d,
                            float* __restrict__ out) {
    __shared__ float sw[NPGv / SPLIT];   // 512
    int part = blockIdx.x & (SPLIT - 1);
    int sb   = blockIdx.x >> 3;          // SPLIT == 8
    int side = sb >> 4;
    int b    = sb & 15;
    const float* x = side ? x_d : x_i;
    const int rows_per = NPGv / SPLIT;   // 512
    int r0 = part * rows_per;
    int nodebase = side * Nn + b * NPGv + r0;
    long long rowbase = (long long)(b * NPGv + r0) * Cc;

    for (int r = threadIdx.x; r < rows_per; r += blockDim.x) sw[r] = g_wt[nodebase + r];
    __syncthreads();

    int cg = threadIdx.x & 63;           // column group: cols cg*4..cg*4+3
    int rg = threadIdx.x >> 6;           // row group 0..3
    float4 acc = make_float4(0.f, 0.f, 0.f, 0.f);
    for (int r = rg; r < rows_per; r += 4) {
        float w = sw[r];
        if (w != 0.f) {
            float4 xv = *reinterpret_cast<const float4*>(x + rowbase + (long long)r * Cc + cg * 4);
            acc.x += w * xv.x; acc.y += w * xv.y;
            acc.z += w * xv.z; acc.w += w * xv.w;
        }
    }
    float* o = &out[b * (2 * Cc) + side * Cc + cg * 4];
    atomicAdd(reinterpret_cast<float2*>(o),     make_float2(acc.x, acc.y));
    atomicAdd(reinterpret_cast<float2*>(o + 2), make_float2(acc.z, acc.w));
}

// ---- launch ----------------------------------------------------------------
extern "C" void kernel_launch(void* const* d_in, const int* in_sizes, int n_in,
                              void* d_out, int out_size) {
    const float* x_inst     = (const float*)d_in[0];
    const float* x_data     = (const float*)d_in[1];
    const float* w_kqv_inst = (const float*)d_in[2];
    const float* b_kqv_inst = (const float*)d_in[3];
    const float* w_kqv_data = (const float*)d_in[4];
    const float* b_kqv_data = (const float*)d_in[5];
    const float* w_out_inst = (const float*)d_in[6];
    const float* b_out_inst = (const float*)d_in[7];
    const float* w_out_data = (const float*)d_in[8];
    const float* b_out_data = (const float*)d_in[9];
    const float* krel_w     = (const float*)d_in[10];
    const float* krel_b     = (const float*)d_in[11];
    const float* vrel_w     = (const float*)d_in[12];
    const float* vrel_b     = (const float*)d_in[13];
    const float* p_rel      = (const float*)d_in[14];
    const int*   ei_i2d     = (const int*)d_in[15];
    const int*   ei_d2i     = (const int*)d_in[16];
    const int*   ei_i2i     = (const int*)d_in[17];
    float* out = (float*)d_out;

    kqv_kernel<<<(2 * Nn) / 8, 256>>>(x_inst, x_data, w_kqv_inst, b_kqv_inst,
                                      w_kqv_data, b_kqv_data);
    edge_kernel<<<3 * (Ee / 512), 256>>>(ei_i2d, ei_d2i, ei_i2i, krel_w, krel_b,
                                         vrel_w, vrel_b, p_rel);
    select_kernel<<<2 * Bb, 1024>>>(w_out_inst, b_out_inst, w_out_data, b_out_data, out);
    pool_kernel<<<2 * Bb * SPLIT, 256>>>(x_inst, x_data, out);
}

// round 6
// speedup vs baseline: 2.6604x; 1.1850x over previous
#include <cuda_runtime.h>
#include <math.h>

// Problem constants (fixed shapes)
namespace {
constexpr int Nn   = 65536;    // B*NPG nodes per side
constexpr int Cc   = 256;      // feature dim
constexpr int Ee   = 1048576;  // edges per edge set
constexpr int Bb   = 16;       // batch
constexpr int NPGv = 4096;     // nodes per graph
constexpr int Kk   = 1024;     // top-k
constexpr int NT   = 131072;   // 2*N
constexpr int PSPLIT = 16;     // pooling splits per (side,batch): 64 rows each
}

// Scratch (device globals: no allocation allowed)
__device__ float2 g_kv[NT];    // (k, v) packed -> one gather sector
__device__ float  g_q[NT];     // compact q table (L1-friendly gathers)
__device__ float2 g_dn[NT];    // (num, den) atomic accumulators
__device__ int    g_sel[2 * Bb * Kk];   // compacted selected row indices (local 0..NPGv-1)
__device__ float  g_selw[2 * Bb * Kk];  // matching weights tanh(score)/K

// ---- float <-> order-preserving uint ------------------------------------
__device__ __forceinline__ unsigned encf(float f) {
    unsigned u = __float_as_uint(f);
    return (u & 0x80000000u) ? ~u : (u | 0x80000000u);
}

// ---- kqv: per-node 3 dot products (warp per node), conflict-free smem ----
// Also zeroes g_dn (runs before edge_kernel).
__global__ void kqv_kernel(const float* __restrict__ x_i, const float* __restrict__ x_d,
                           const float* __restrict__ w_i, const float* __restrict__ b_i,
                           const float* __restrict__ w_d, const float* __restrict__ b_d) {
    __shared__ float4 sw0[Cc / 4], sw1[Cc / 4], sw2[Cc / 4];
    __shared__ float  sb[3];
    int node0 = blockIdx.x * 8;          // 8 warps per block, one node per warp
    int side  = (node0 >= Nn) ? 1 : 0;   // Nn % 8 == 0 -> block never straddles
    const float* w  = side ? w_d : w_i;
    const float* bb = side ? b_d : b_i;
    for (int c = threadIdx.x; c < Cc; c += blockDim.x) {
        reinterpret_cast<float*>(sw0)[c] = w[c * 3 + 0];
        reinterpret_cast<float*>(sw1)[c] = w[c * 3 + 1];
        reinterpret_cast<float*>(sw2)[c] = w[c * 3 + 2];
    }
    if (threadIdx.x < 3) sb[threadIdx.x] = bb[threadIdx.x];
    __syncthreads();

    int warp = threadIdx.x >> 5;
    int lane = threadIdx.x & 31;
    int node = node0 + warp;
    const float* x = side ? (x_d + (long long)(node - Nn) * Cc)
                          : (x_i + (long long)node * Cc);
    float s0 = 0.f, s1 = 0.f, s2 = 0.f;
#pragma unroll
    for (int h = 0; h < 2; ++h) {
        int ci = lane + h * 32;                    // float4 index
        float4 xv = *reinterpret_cast<const float4*>(x + ci * 4);
        float4 w0 = sw0[ci], w1 = sw1[ci], w2 = sw2[ci];
        s0 += xv.x * w0.x + xv.y * w0.y + xv.z * w0.z + xv.w * w0.w;
        s1 += xv.x * w1.x + xv.y * w1.y + xv.z * w1.z + xv.w * w1.w;
        s2 += xv.x * w2.x + xv.y * w2.y + xv.z * w2.z + xv.w * w2.w;
    }
#pragma unroll
    for (int o = 16; o; o >>= 1) {
        s0 += __shfl_down_sync(0xFFFFFFFFu, s0, o);
        s1 += __shfl_down_sync(0xFFFFFFFFu, s1, o);
        s2 += __shfl_down_sync(0xFFFFFFFFu, s2, o);
    }
    if (lane == 0) {
        g_kv[node] = make_float2(s0 + sb[0], s2 + sb[2]);   // (k, v)
        g_q[node]  = s1 + sb[1];
        g_dn[node] = make_float2(0.f, 0.f);
    }
}

// ---- single fused edge pass: exp(logit) sums, no max-shift -----------------
__global__ void edge_kernel(const int* __restrict__ ei0, const int* __restrict__ ei1,
                            const int* __restrict__ ei2,
                            const float* __restrict__ krel_w, const float* __restrict__ krel_b,
                            const float* __restrict__ vrel_w, const float* __restrict__ vrel_b,
                            const float* __restrict__ p_rel) {
    int t  = blockIdx.x >> 11;                                 // 0,1,2 (uniform per block)
    int gi = ((blockIdx.x & 2047) << 8) | threadIdx.x;         // int2 index, 0..Ee/2-1
    const int* ei = (t == 0) ? ei0 : ((t == 1) ? ei1 : ei2);
    int2 ss = __ldg(reinterpret_cast<const int2*>(ei) + gi);
    int2 dd = __ldg(reinterpret_cast<const int2*>(ei + Ee) + gi);
    int sbase = (t == 1) ? Nn : 0;
    int dbase = (t == 0) ? Nn : 0;
    float kw = krel_w[t], kb = krel_b[t];
    float vw = vrel_w[t], vb = vrel_b[t];
    float pr = p_rel[t];

    int dg0 = dbase + dd.x, dg1 = dbase + dd.y;
    float2 kv0 = __ldg(&g_kv[sbase + ss.x]);
    float2 kv1 = __ldg(&g_kv[sbase + ss.y]);
    float  q0  = __ldg(&g_q[dg0]);
    float  q1  = __ldg(&g_q[dg1]);

    float ex0 = __expf(q0 * (kv0.x * kw + kb) * pr);
    float ex1 = __expf(q1 * (kv1.x * kw + kb) * pr);
    float ve0 = kv0.y * vw + vb;
    float ve1 = kv1.y * vw + vb;
    atomicAdd(&g_dn[dg0], make_float2(ex0 * ve0, ex0));
    atomicAdd(&g_dn[dg1], make_float2(ex1 * ve1, ex1));
}

// ---- score + per-batch top-K (radix select) + compaction -------------------
// Produces the dense (row, weight) list for pooling; zeroes out slice.
__global__ void select_kernel(const float* __restrict__ w_out_i, const float* __restrict__ b_out_i,
                              const float* __restrict__ w_out_d, const float* __restrict__ b_out_d,
                              float* __restrict__ out) {
    constexpr int T = 1024;
    constexpr int CHUNK = NPGv / T;   // 4
    __shared__ unsigned skey[NPGv];
    __shared__ float    sval[NPGv];
    __shared__ int      hist[256];
    __shared__ int      s_sel, s_rem;
    __shared__ int      warp_sums[32];
    int tid  = threadIdx.x;
    int side = blockIdx.x >> 4;      // 0..1
    int b    = blockIdx.x & 15;      // 0..15
    int base = side * Nn + b * NPGv;
    int obase = (side * Bb + b) * Kk;
    float wo = side ? w_out_d[0] : w_out_i[0];
    float bo = side ? b_out_d[0] : b_out_i[0];

    if (tid < Cc) out[b * (2 * Cc) + side * Cc + tid] = 0.f;   // zero own out slice

    for (int j = tid; j < NPGv; j += T) {
        float2 dn = g_dn[base + j];
        float a   = (dn.y > 0.f) ? (dn.x / dn.y) : 0.f;   // empty segment -> 0
        float z   = a * wo + bo;
        float sc  = 0.5f * z * (1.f + erff(z * 0.70710678118654752f));  // exact gelu
        sval[j] = sc;
        skey[j] = encf(sc);
    }
    if (tid == 0) s_rem = Kk;

    // 4-pass radix select for the Kk-th largest key
    unsigned prefix = 0u;
#pragma unroll
    for (int shift = 24; shift >= 0; shift -= 8) {
        unsigned umask = (shift == 24) ? 0u : (0xFFFFFFFFu << (shift + 8));
        __syncthreads();
        if (tid < 256) hist[tid] = 0;
        __syncthreads();
#pragma unroll
        for (int u = 0; u < CHUNK; ++u) {
            unsigned key = skey[tid + u * T];
            bool act = (key & umask) == (prefix & umask);
            if (act) {
                unsigned bin   = (key >> shift) & 255u;
                unsigned peers = __match_any_sync(__activemask(), bin);
                int leader = __ffs(peers) - 1;
                if ((tid & 31) == leader) atomicAdd(&hist[bin], __popc(peers));
            }
        }
        __syncthreads();
        if (tid < 32) {
            int rem = s_rem;
            int h[8], sfx[8];
            int bin0 = tid * 8;
#pragma unroll
            for (int j = 0; j < 8; ++j) h[j] = hist[bin0 + j];
            sfx[7] = h[7];
#pragma unroll
            for (int j = 6; j >= 0; --j) sfx[j] = h[j] + sfx[j + 1];
            int tot = sfx[0];
            int suf = tot;
#pragma unroll
            for (int off = 1; off < 32; off <<= 1) {
                int v = __shfl_down_sync(0xFFFFFFFFu, suf, off);
                if (tid + off < 32) suf += v;
            }
            int above_lane = suf - tot;   // sum of bins >= (tid+1)*8
#pragma unroll
            for (int j = 0; j < 8; ++j) {
                int cnt_ge    = sfx[j] + above_lane;
                int cnt_above = (j == 7) ? above_lane : (sfx[j + 1] + above_lane);
                if (cnt_ge >= rem && cnt_above < rem) {
                    s_sel = bin0 + j;
                    s_rem = rem - cnt_above;
                }
            }
        }
        __syncthreads();
        prefix |= ((unsigned)s_sel) << shift;
    }
    unsigned thr = prefix;           // Kk-th largest key
    int need_eq = s_rem;             // #ties at thr to keep (lowest index first)

    int lane = tid & 31, warp = tid >> 5;
    // block-wide exclusive scan helper over per-thread counts
    auto excl_scan = [&](int cnt) -> int {
        int incl = cnt;
#pragma unroll
        for (int off = 1; off < 32; off <<= 1) {
            int v = __shfl_up_sync(0xFFFFFFFFu, incl, off);
            if (lane >= off) incl += v;
        }
        if (lane == 31) warp_sums[warp] = incl;
        __syncthreads();
        if (tid < 32) {
            int v = warp_sums[tid];
#pragma unroll
            for (int off = 1; off < 32; off <<= 1) {
                int t2 = __shfl_up_sync(0xFFFFFFFFu, v, off);
                if (tid >= off) v += t2;
            }
            warp_sums[tid] = v;
        }
        __syncthreads();
        return incl - cnt + (warp ? warp_sums[warp - 1] : 0);
    };

    // tie-rank scan (ascending index over keys == thr)
    int j0 = tid * CHUNK;
    int myties = 0;
#pragma unroll
    for (int u = 0; u < CHUNK; ++u) myties += (skey[j0 + u] == thr) ? 1 : 0;
    int r = excl_scan(myties);

    // selection flags + count
    unsigned selmask = 0u;
    int nsel = 0;
#pragma unroll
    for (int u = 0; u < CHUNK; ++u) {
        unsigned key = skey[j0 + u];
        bool sel = key > thr;
        if (key == thr) { sel = (r < need_eq); ++r; }
        if (sel) { selmask |= (1u << u); ++nsel; }
    }
    __syncthreads();                 // warp_sums reuse
    int pos = excl_scan(nsel);

    // compact (row, weight) pairs
#pragma unroll
    for (int u = 0; u < CHUNK; ++u) {
        if (selmask & (1u << u)) {
            int j = j0 + u;
            g_sel[obase + pos]  = j;
            g_selw[obase + pos] = tanhf(sval[j]) * (1.f / (float)Kk);
            ++pos;
        }
    }
}

// ---- pooling: dense weighted sum over compacted top-K rows -----------------
__global__ void pool_kernel(const float* __restrict__ x_i, const float* __restrict__ x_d,
                            float* __restrict__ out) {
    constexpr int RPB = Kk / PSPLIT;     // 64 rows per block
    __shared__ int   sidx[RPB];
    __shared__ float swt[RPB];
    int part = blockIdx.x & (PSPLIT - 1);
    int sb   = blockIdx.x >> 4;          // PSPLIT == 16
    int side = sb >> 4;
    int b    = sb & 15;
    const float* x = side ? x_d : x_i;
    int obase = (side * Bb + b) * Kk + part * RPB;
    long long xgbase = (long long)b * NPGv * Cc;

    if (threadIdx.x < RPB) {
        sidx[threadIdx.x] = g_sel[obase + threadIdx.x];
        swt[threadIdx.x]  = g_selw[obase + threadIdx.x];
    }
    __syncthreads();

    int cg = threadIdx.x & 63;           // float4 column group
    int rg = threadIdx.x >> 6;           // row group 0..3
    float4 acc = make_float4(0.f, 0.f, 0.f, 0.f);
#pragma unroll 4
    for (int r = rg; r < RPB; r += 4) {
        int   row = sidx[r];
        float w   = swt[r];
        float4 xv = *reinterpret_cast<const float4*>(x + xgbase + (long long)row * Cc + cg * 4);
        acc.x += w * xv.x; acc.y += w * xv.y;
        acc.z += w * xv.z; acc.w += w * xv.w;
    }
    float* o = &out[b * (2 * Cc) + side * Cc + cg * 4];
    atomicAdd(reinterpret_cast<float2*>(o),     make_float2(acc.x, acc.y));
    atomicAdd(reinterpret_cast<float2*>(o + 2), make_float2(acc.z, acc.w));
}

// ---- launch ----------------------------------------------------------------
extern "C" void kernel_launch(void* const* d_in, const int* in_sizes, int n_in,
                              void* d_out, int out_size) {
    const float* x_inst     = (const float*)d_in[0];
    const float* x_data     = (const float*)d_in[1];
    const float* w_kqv_inst = (const float*)d_in[2];
    const float* b_kqv_inst = (const float*)d_in[3];
    const float* w_kqv_data = (const float*)d_in[4];
    const float* b_kqv_data = (const float*)d_in[5];
    const float* w_out_inst = (const float*)d_in[6];
    const float* b_out_inst = (const float*)d_in[7];
    const float* w_out_data = (const float*)d_in[8];
    const float* b_out_data = (const float*)d_in[9];
    const float* krel_w     = (const float*)d_in[10];
    const float* krel_b     = (const float*)d_in[11];
    const float* vrel_w     = (const float*)d_in[12];
    const float* vrel_b     = (const float*)d_in[13];
    const float* p_rel      = (const float*)d_in[14];
    const int*   ei_i2d     = (const int*)d_in[15];
    const int*   ei_d2i     = (const int*)d_in[16];
    const int*   ei_i2i     = (const int*)d_in[17];
    float* out = (float*)d_out;

    kqv_kernel<<<(2 * Nn) / 8, 256>>>(x_inst, x_data, w_kqv_inst, b_kqv_inst,
                                      w_kqv_data, b_kqv_data);
    edge_kernel<<<3 * (Ee / 512), 256>>>(ei_i2d, ei_d2i, ei_i2i, krel_w, krel_b,
                                         vrel_w, vrel_b, p_rel);
    select_kernel<<<2 * Bb, 1024>>>(w_out_inst, b_out_inst, w_out_data, b_out_data, out);
    pool_kernel<<<2 * Bb * PSPLIT, 256>>>(x_inst, x_data, out);
}

// round 7
// speedup vs baseline: 2.8204x; 1.0601x over previous
#include <cuda_runtime.h>
#include <math.h>

// Problem constants (fixed shapes)
namespace {
constexpr int Nn   = 65536;    // B*NPG nodes per side
constexpr int Cc   = 256;      // feature dim
constexpr int Ee   = 1048576;  // edges per edge set
constexpr int Bb   = 16;       // batch
constexpr int NPGv = 4096;     // nodes per graph
constexpr int Kk   = 1024;     // top-k
constexpr int NT   = 131072;   // 2*N
constexpr int PSPLIT = 32;     // pooling splits per (side,batch): 32 rows each
}

// Scratch (device globals: no allocation allowed)
__device__ float2 g_kv[NT];    // (k, v) packed -> one gather sector
__device__ float  g_q[NT];     // compact q table (L1-friendly gathers)
__device__ float2 g_dn[NT];    // (num, den) atomic accumulators
__device__ int    g_sel[2 * Bb * Kk];   // compacted selected row indices (local)
__device__ float  g_selw[2 * Bb * Kk];  // matching weights tanh(score)/K

// ---- float <-> order-preserving uint ------------------------------------
__device__ __forceinline__ unsigned encf(float f) {
    unsigned u = __float_as_uint(f);
    return (u & 0x80000000u) ? ~u : (u | 0x80000000u);
}

// ---- kqv: 4 nodes per warp, 8 loads in flight, conflict-free smem ---------
// Also zeroes g_dn (runs before edge_kernel).
__global__ void kqv_kernel(const float* __restrict__ x_i, const float* __restrict__ x_d,
                           const float* __restrict__ w_i, const float* __restrict__ b_i,
                           const float* __restrict__ w_d, const float* __restrict__ b_d) {
    __shared__ float4 sw0[Cc / 4], sw1[Cc / 4], sw2[Cc / 4];
    __shared__ float  sb[3];
    int node0 = blockIdx.x * 32;         // 8 warps x 4 nodes per block
    int side  = (node0 >= Nn) ? 1 : 0;   // Nn % 32 == 0 -> block never straddles
    const float* w  = side ? w_d : w_i;
    const float* bb = side ? b_d : b_i;
    for (int c = threadIdx.x; c < Cc; c += blockDim.x) {
        reinterpret_cast<float*>(sw0)[c] = w[c * 3 + 0];
        reinterpret_cast<float*>(sw1)[c] = w[c * 3 + 1];
        reinterpret_cast<float*>(sw2)[c] = w[c * 3 + 2];
    }
    if (threadIdx.x < 3) sb[threadIdx.x] = bb[threadIdx.x];
    __syncthreads();

    int warp = threadIdx.x >> 5;
    int lane = threadIdx.x & 31;
    int nbase = node0 + warp * 4;
    const float* x = side ? (x_d + (long long)(nbase - Nn) * Cc)
                          : (x_i + (long long)nbase * Cc);

    // issue all 8 independent loads first (MLP=8)
    float4 xv[4][2];
#pragma unroll
    for (int n = 0; n < 4; ++n)
#pragma unroll
        for (int h = 0; h < 2; ++h)
            xv[n][h] = *reinterpret_cast<const float4*>(x + n * Cc + (lane + h * 32) * 4);

#pragma unroll
    for (int n = 0; n < 4; ++n) {
        float s0 = 0.f, s1 = 0.f, s2 = 0.f;
#pragma unroll
        for (int h = 0; h < 2; ++h) {
            int ci = lane + h * 32;
            float4 v  = xv[n][h];
            float4 w0 = sw0[ci], w1 = sw1[ci], w2 = sw2[ci];
            s0 += v.x * w0.x + v.y * w0.y + v.z * w0.z + v.w * w0.w;
            s1 += v.x * w1.x + v.y * w1.y + v.z * w1.z + v.w * w1.w;
            s2 += v.x * w2.x + v.y * w2.y + v.z * w2.z + v.w * w2.w;
        }
#pragma unroll
        for (int o = 16; o; o >>= 1) {
            s0 += __shfl_down_sync(0xFFFFFFFFu, s0, o);
            s1 += __shfl_down_sync(0xFFFFFFFFu, s1, o);
            s2 += __shfl_down_sync(0xFFFFFFFFu, s2, o);
        }
        if (lane == 0) {
            int node = nbase + n;
            g_kv[node] = make_float2(s0 + sb[0], s2 + sb[2]);   // (k, v)
            g_q[node]  = s1 + sb[1];
            g_dn[node] = make_float2(0.f, 0.f);
        }
    }
}

// ---- single fused edge pass: 4 edges/thread, exp sums, no max-shift --------
__global__ void edge_kernel(const int* __restrict__ ei0, const int* __restrict__ ei1,
                            const int* __restrict__ ei2,
                            const float* __restrict__ krel_w, const float* __restrict__ krel_b,
                            const float* __restrict__ vrel_w, const float* __restrict__ vrel_b,
                            const float* __restrict__ p_rel) {
    int t  = blockIdx.x >> 10;                                 // 0,1,2 (uniform per block)
    int gi = ((blockIdx.x & 1023) << 8) | threadIdx.x;         // int4 index, 0..Ee/4-1
    const int* ei = (t == 0) ? ei0 : ((t == 1) ? ei1 : ei2);
    int4 ss = __ldg(reinterpret_cast<const int4*>(ei) + gi);
    int4 dd = __ldg(reinterpret_cast<const int4*>(ei + Ee) + gi);
    int sbase = (t == 1) ? Nn : 0;
    int dbase = (t == 0) ? Nn : 0;
    float kw = krel_w[t], kb = krel_b[t];
    float vw = vrel_w[t], vb = vrel_b[t];
    float pr = p_rel[t];

    int s[4] = {ss.x, ss.y, ss.z, ss.w};
    int d[4] = {dd.x, dd.y, dd.z, dd.w};
    float2 kv[4];
    float  q[4];
#pragma unroll
    for (int u = 0; u < 4; ++u) kv[u] = __ldg(&g_kv[sbase + s[u]]);
#pragma unroll
    for (int u = 0; u < 4; ++u) q[u]  = __ldg(&g_q[dbase + d[u]]);
#pragma unroll
    for (int u = 0; u < 4; ++u) {
        float ex = __expf(q[u] * (kv[u].x * kw + kb) * pr);
        float ve = kv[u].y * vw + vb;
        atomicAdd(&g_dn[dbase + d[u]], make_float2(ex * ve, ex));
    }
}

// ---- score + per-batch top-K (radix select) + compaction -------------------
__global__ void select_kernel(const float* __restrict__ w_out_i, const float* __restrict__ b_out_i,
                              const float* __restrict__ w_out_d, const float* __restrict__ b_out_d,
                              float* __restrict__ out) {
    constexpr int T = 1024;
    constexpr int CHUNK = NPGv / T;   // 4
    __shared__ unsigned skey[NPGv];
    __shared__ float    sval[NPGv];
    __shared__ int      hist[256];
    __shared__ int      s_sel, s_rem;
    __shared__ int      warp_sums[32];
    int tid  = threadIdx.x;
    int side = blockIdx.x >> 4;      // 0..1
    int b    = blockIdx.x & 15;      // 0..15
    int base = side * Nn + b * NPGv;
    int obase = (side * Bb + b) * Kk;
    float wo = side ? w_out_d[0] : w_out_i[0];
    float bo = side ? b_out_d[0] : b_out_i[0];

    if (tid < Cc) out[b * (2 * Cc) + side * Cc + tid] = 0.f;   // zero own out slice

    for (int j = tid; j < NPGv; j += T) {
        float2 dn = g_dn[base + j];
        float a   = (dn.y > 0.f) ? (dn.x / dn.y) : 0.f;   // empty segment -> 0
        float z   = a * wo + bo;
        float sc  = 0.5f * z * (1.f + erff(z * 0.70710678118654752f));  // exact gelu
        sval[j] = sc;
        skey[j] = encf(sc);
    }
    if (tid == 0) s_rem = Kk;

    // 4-pass radix select for the Kk-th largest key
    unsigned prefix = 0u;
#pragma unroll
    for (int shift = 24; shift >= 0; shift -= 8) {
        unsigned umask = (shift == 24) ? 0u : (0xFFFFFFFFu << (shift + 8));
        __syncthreads();
        if (tid < 256) hist[tid] = 0;
        __syncthreads();
#pragma unroll
        for (int u = 0; u < CHUNK; ++u) {
            unsigned key = skey[tid + u * T];
            bool act = (key & umask) == (prefix & umask);
            if (act) {
                unsigned bin   = (key >> shift) & 255u;
                unsigned peers = __match_any_sync(__activemask(), bin);
                int leader = __ffs(peers) - 1;
                if ((tid & 31) == leader) atomicAdd(&hist[bin], __popc(peers));
            }
        }
        __syncthreads();
        if (tid < 32) {
            int rem = s_rem;
            int h[8], sfx[8];
            int bin0 = tid * 8;
#pragma unroll
            for (int j = 0; j < 8; ++j) h[j] = hist[bin0 + j];
            sfx[7] = h[7];
#pragma unroll
            for (int j = 6; j >= 0; --j) sfx[j] = h[j] + sfx[j + 1];
            int tot = sfx[0];
            int suf = tot;
#pragma unroll
            for (int off = 1; off < 32; off <<= 1) {
                int v = __shfl_down_sync(0xFFFFFFFFu, suf, off);
                if (tid + off < 32) suf += v;
            }
            int above_lane = suf - tot;   // sum of bins >= (tid+1)*8
#pragma unroll
            for (int j = 0; j < 8; ++j) {
                int cnt_ge    = sfx[j] + above_lane;
                int cnt_above = (j == 7) ? above_lane : (sfx[j + 1] + above_lane);
                if (cnt_ge >= rem && cnt_above < rem) {
                    s_sel = bin0 + j;
                    s_rem = rem - cnt_above;
                }
            }
        }
        __syncthreads();
        prefix |= ((unsigned)s_sel) << shift;
    }
    unsigned thr = prefix;           // Kk-th largest key
    int need_eq = s_rem;             // #ties at thr to keep (lowest index first)

    int lane = tid & 31, warp = tid >> 5;
    auto excl_scan = [&](int cnt) -> int {
        int incl = cnt;
#pragma unroll
        for (int off = 1; off < 32; off <<= 1) {
            int v = __shfl_up_sync(0xFFFFFFFFu, incl, off);
            if (lane >= off) incl += v;
        }
        if (lane == 31) warp_sums[warp] = incl;
        __syncthreads();
        if (tid < 32) {
            int v = warp_sums[tid];
#pragma unroll
            for (int off = 1; off < 32; off <<= 1) {
                int t2 = __shfl_up_sync(0xFFFFFFFFu, v, off);
                if (tid >= off) v += t2;
            }
            warp_sums[tid] = v;
        }
        __syncthreads();
        return incl - cnt + (warp ? warp_sums[warp - 1] : 0);
    };

    // tie-rank scan (ascending index over keys == thr)
    int j0 = tid * CHUNK;
    int myties = 0;
#pragma unroll
    for (int u = 0; u < CHUNK; ++u) myties += (skey[j0 + u] == thr) ? 1 : 0;
    int r = excl_scan(myties);

    unsigned selmask = 0u;
    int nsel = 0;
#pragma unroll
    for (int u = 0; u < CHUNK; ++u) {
        unsigned key = skey[j0 + u];
        bool sel = key > thr;
        if (key == thr) { sel = (r < need_eq); ++r; }
        if (sel) { selmask |= (1u << u); ++nsel; }
    }
    __syncthreads();                 // warp_sums reuse
    int pos = excl_scan(nsel);

#pragma unroll
    for (int u = 0; u < CHUNK; ++u) {
        if (selmask & (1u << u)) {
            int j = j0 + u;
            g_sel[obase + pos]  = j;
            g_selw[obase + pos] = tanhf(sval[j]) * (1.f / (float)Kk);
            ++pos;
        }
    }
}

// ---- pooling: dense weighted sum over compacted top-K rows -----------------
__global__ void pool_kernel(const float* __restrict__ x_i, const float* __restrict__ x_d,
                            float* __restrict__ out) {
    constexpr int RPB = Kk / PSPLIT;     // 32 rows per block
    __shared__ int   sidx[RPB];
    __shared__ float swt[RPB];
    int part = blockIdx.x & (PSPLIT - 1);
    int sb   = blockIdx.x >> 5;          // PSPLIT == 32
    int side = sb >> 4;
    int b    = sb & 15;
    const float* x = side ? x_d : x_i;
    int obase = (side * Bb + b) * Kk + part * RPB;
    long long xgbase = (long long)b * NPGv * Cc;

    if (threadIdx.x < RPB) {
        sidx[threadIdx.x] = g_sel[obase + threadIdx.x];
        swt[threadIdx.x]  = g_selw[obase + threadIdx.x];
    }
    __syncthreads();

    int cg = threadIdx.x & 63;           // float4 column group
    int rg = threadIdx.x >> 6;           // row group 0..3
    float4 acc = make_float4(0.f, 0.f, 0.f, 0.f);
#pragma unroll 8
    for (int r = rg; r < RPB; r += 4) {
        int   row = sidx[r];
        float w   = swt[r];
        float4 xv = *reinterpret_cast<const float4*>(x + xgbase + (long long)row * Cc + cg * 4);
        acc.x += w * xv.x; acc.y += w * xv.y;
        acc.z += w * xv.z; acc.w += w * xv.w;
    }
    float* o = &out[b * (2 * Cc) + side * Cc + cg * 4];
    atomicAdd(reinterpret_cast<float2*>(o),     make_float2(acc.x, acc.y));
    atomicAdd(reinterpret_cast<float2*>(o + 2), make_float2(acc.z, acc.w));
}

// ---- launch ----------------------------------------------------------------
extern "C" void kernel_launch(void* const* d_in, const int* in_sizes, int n_in,
                              void* d_out, int out_size) {
    const float* x_inst     = (const float*)d_in[0];
    const float* x_data     = (const float*)d_in[1];
    const float* w_kqv_inst = (const float*)d_in[2];
    const float* b_kqv_inst = (const float*)d_in[3];
    const float* w_kqv_data = (const float*)d_in[4];
    const float* b_kqv_data = (const float*)d_in[5];
    const float* w_out_inst = (const float*)d_in[6];
    const float* b_out_inst = (const float*)d_in[7];
    const float* w_out_data = (const float*)d_in[8];
    const float* b_out_data = (const float*)d_in[9];
    const float* krel_w     = (const float*)d_in[10];
    const float* krel_b     = (const float*)d_in[11];
    const float* vrel_w     = (const float*)d_in[12];
    const float* vrel_b     = (const float*)d_in[13];
    const float* p_rel      = (const float*)d_in[14];
    const int*   ei_i2d     = (const int*)d_in[15];
    const int*   ei_d2i     = (const int*)d_in[16];
    const int*   ei_i2i     = (const int*)d_in[17];
    float* out = (float*)d_out;

    kqv_kernel<<<(2 * Nn) / 32, 256>>>(x_inst, x_data, w_kqv_inst, b_kqv_inst,
                                       w_kqv_data, b_kqv_data);
    edge_kernel<<<3 * (Ee / 1024), 256>>>(ei_i2d, ei_d2i, ei_i2i, krel_w, krel_b,
                                          vrel_w, vrel_b, p_rel);
    select_kernel<<<2 * Bb, 1024>>>(w_out_inst, b_out_inst, w_out_data, b_out_data, out);
    pool_kernel<<<2 * Bb * PSPLIT, 256>>>(x_inst, x_data, out);
}

// round 8
// speedup vs baseline: 2.8498x; 1.0104x over previous
#include <cuda_runtime.h>
#include <math.h>

// Problem constants (fixed shapes)
namespace {
constexpr int Nn   = 65536;    // B*NPG nodes per side
constexpr int Cc   = 256;      // feature dim
constexpr int Ee   = 1048576;  // edges per edge set
constexpr int Bb   = 16;       // batch
constexpr int NPGv = 4096;     // nodes per graph
constexpr int Kk   = 1024;     // top-k
constexpr int NT   = 131072;   // 2*N
constexpr int PSPLIT = 16;     // pooling splits per (side,batch): 64 rows each
}

// Scratch (device globals: no allocation allowed)
__device__ float2 g_kv[NT];    // (k, v) packed -> one gather sector
__device__ float  g_q[NT];     // compact q table (L1-friendly gathers)
__device__ float2 g_dn[NT];    // (num, den) atomic accumulators
__device__ int    g_sel[2 * Bb * Kk];   // compacted selected row indices (local)
__device__ float  g_selw[2 * Bb * Kk];  // matching weights tanh(score)/K

// ---- float <-> order-preserving uint ------------------------------------
__device__ __forceinline__ unsigned encf(float f) {
    unsigned u = __float_as_uint(f);
    return (u & 0x80000000u) ? ~u : (u | 0x80000000u);
}

// ---- kqv: 4 nodes per warp, 8 loads in flight, conflict-free smem ---------
// Also zeroes g_dn (runs before edge_kernel).
__global__ void kqv_kernel(const float* __restrict__ x_i, const float* __restrict__ x_d,
                           const float* __restrict__ w_i, const float* __restrict__ b_i,
                           const float* __restrict__ w_d, const float* __restrict__ b_d) {
    __shared__ float4 sw0[Cc / 4], sw1[Cc / 4], sw2[Cc / 4];
    __shared__ float  sb[3];
    int node0 = blockIdx.x * 32;         // 8 warps x 4 nodes per block
    int side  = (node0 >= Nn) ? 1 : 0;   // Nn % 32 == 0 -> block never straddles
    const float* w  = side ? w_d : w_i;
    const float* bb = side ? b_d : b_i;
    for (int c = threadIdx.x; c < Cc; c += blockDim.x) {
        reinterpret_cast<float*>(sw0)[c] = w[c * 3 + 0];
        reinterpret_cast<float*>(sw1)[c] = w[c * 3 + 1];
        reinterpret_cast<float*>(sw2)[c] = w[c * 3 + 2];
    }
    if (threadIdx.x < 3) sb[threadIdx.x] = bb[threadIdx.x];
    __syncthreads();

    int warp = threadIdx.x >> 5;
    int lane = threadIdx.x & 31;
    int nbase = node0 + warp * 4;
    const float* x = side ? (x_d + (long long)(nbase - Nn) * Cc)
                          : (x_i + (long long)nbase * Cc);

    // issue all 8 independent loads first (MLP=8)
    float4 xv[4][2];
#pragma unroll
    for (int n = 0; n < 4; ++n)
#pragma unroll
        for (int h = 0; h < 2; ++h)
            xv[n][h] = *reinterpret_cast<const float4*>(x + n * Cc + (lane + h * 32) * 4);

#pragma unroll
    for (int n = 0; n < 4; ++n) {
        float s0 = 0.f, s1 = 0.f, s2 = 0.f;
#pragma unroll
        for (int h = 0; h < 2; ++h) {
            int ci = lane + h * 32;
            float4 v  = xv[n][h];
            float4 w0 = sw0[ci], w1 = sw1[ci], w2 = sw2[ci];
            s0 += v.x * w0.x + v.y * w0.y + v.z * w0.z + v.w * w0.w;
            s1 += v.x * w1.x + v.y * w1.y + v.z * w1.z + v.w * w1.w;
            s2 += v.x * w2.x + v.y * w2.y + v.z * w2.z + v.w * w2.w;
        }
#pragma unroll
        for (int o = 16; o; o >>= 1) {
            s0 += __shfl_down_sync(0xFFFFFFFFu, s0, o);
            s1 += __shfl_down_sync(0xFFFFFFFFu, s1, o);
            s2 += __shfl_down_sync(0xFFFFFFFFu, s2, o);
        }
        if (lane == 0) {
            int node = nbase + n;
            g_kv[node] = make_float2(s0 + sb[0], s2 + sb[2]);   // (k, v)
            g_q[node]  = s1 + sb[1];
            g_dn[node] = make_float2(0.f, 0.f);
        }
    }
}

// ---- single fused edge pass: 8 edges/thread, exp sums, no max-shift --------
__global__ void edge_kernel(const int* __restrict__ ei0, const int* __restrict__ ei1,
                            const int* __restrict__ ei2,
                            const float* __restrict__ krel_w, const float* __restrict__ krel_b,
                            const float* __restrict__ vrel_w, const float* __restrict__ vrel_b,
                            const float* __restrict__ p_rel) {
    int t  = blockIdx.x >> 9;                                  // 0,1,2 (uniform per block)
    int gi = ((blockIdx.x & 511) << 8) | threadIdx.x;          // 8-edge group, 0..Ee/8-1
    const int* ei = (t == 0) ? ei0 : ((t == 1) ? ei1 : ei2);
    const int4* sp = reinterpret_cast<const int4*>(ei) + gi * 2;
    const int4* dp = reinterpret_cast<const int4*>(ei + Ee) + gi * 2;
    int4 ss0 = __ldg(sp), ss1 = __ldg(sp + 1);
    int4 dd0 = __ldg(dp), dd1 = __ldg(dp + 1);
    int sbase = (t == 1) ? Nn : 0;
    int dbase = (t == 0) ? Nn : 0;
    float kw = krel_w[t], kb = krel_b[t];
    float vw = vrel_w[t], vb = vrel_b[t];
    float pr = p_rel[t];

    int s[8] = {ss0.x, ss0.y, ss0.z, ss0.w, ss1.x, ss1.y, ss1.z, ss1.w};
    int d[8] = {dd0.x, dd0.y, dd0.z, dd0.w, dd1.x, dd1.y, dd1.z, dd1.w};
    float2 kv[8];
    float  q[8];
#pragma unroll
    for (int u = 0; u < 8; ++u) kv[u] = __ldg(&g_kv[sbase + s[u]]);
#pragma unroll
    for (int u = 0; u < 8; ++u) q[u]  = __ldg(&g_q[dbase + d[u]]);
#pragma unroll
    for (int u = 0; u < 8; ++u) {
        float ex = __expf(q[u] * (kv[u].x * kw + kb) * pr);
        float ve = kv[u].y * vw + vb;
        atomicAdd(&g_dn[dbase + d[u]], make_float2(ex * ve, ex));
    }
}

// ---- score + per-batch top-K (radix select) + compaction -------------------
__global__ void select_kernel(const float* __restrict__ w_out_i, const float* __restrict__ b_out_i,
                              const float* __restrict__ w_out_d, const float* __restrict__ b_out_d,
                              float* __restrict__ out) {
    constexpr int T = 1024;
    constexpr int CHUNK = NPGv / T;   // 4
    __shared__ unsigned skey[NPGv];
    __shared__ float    sval[NPGv];
    __shared__ int      hist[256];
    __shared__ int      s_sel, s_rem;
    __shared__ int      warp_sums[32];
    int tid  = threadIdx.x;
    int side = blockIdx.x >> 4;      // 0..1
    int b    = blockIdx.x & 15;      // 0..15
    int base = side * Nn + b * NPGv;
    int obase = (side * Bb + b) * Kk;
    float wo = side ? w_out_d[0] : w_out_i[0];
    float bo = side ? b_out_d[0] : b_out_i[0];

    if (tid < Cc) out[b * (2 * Cc) + side * Cc + tid] = 0.f;   // zero own out slice

    for (int j = tid; j < NPGv; j += T) {
        float2 dn = g_dn[base + j];
        float a   = (dn.y > 0.f) ? (dn.x / dn.y) : 0.f;   // empty segment -> 0
        float z   = a * wo + bo;
        float sc  = 0.5f * z * (1.f + erff(z * 0.70710678118654752f));  // exact gelu
        sval[j] = sc;
        skey[j] = encf(sc);
    }
    if (tid == 0) s_rem = Kk;

    // 4-pass radix select for the Kk-th largest key
    unsigned prefix = 0u;
#pragma unroll
    for (int shift = 24; shift >= 0; shift -= 8) {
        unsigned umask = (shift == 24) ? 0u : (0xFFFFFFFFu << (shift + 8));
        __syncthreads();
        if (tid < 256) hist[tid] = 0;
        __syncthreads();
#pragma unroll
        for (int u = 0; u < CHUNK; ++u) {
            unsigned key = skey[tid + u * T];
            bool act = (key & umask) == (prefix & umask);
            if (act) {
                unsigned bin   = (key >> shift) & 255u;
                unsigned peers = __match_any_sync(__activemask(), bin);
                int leader = __ffs(peers) - 1;
                if ((tid & 31) == leader) atomicAdd(&hist[bin], __popc(peers));
            }
        }
        __syncthreads();
        if (tid < 32) {
            int rem = s_rem;
            int h[8], sfx[8];
            int bin0 = tid * 8;
#pragma unroll
            for (int j = 0; j < 8; ++j) h[j] = hist[bin0 + j];
            sfx[7] = h[7];
#pragma unroll
            for (int j = 6; j >= 0; --j) sfx[j] = h[j] + sfx[j + 1];
            int tot = sfx[0];
            int suf = tot;
#pragma unroll
            for (int off = 1; off < 32; off <<= 1) {
                int v = __shfl_down_sync(0xFFFFFFFFu, suf, off);
                if (tid + off < 32) suf += v;
            }
            int above_lane = suf - tot;   // sum of bins >= (tid+1)*8
#pragma unroll
            for (int j = 0; j < 8; ++j) {
                int cnt_ge    = sfx[j] + above_lane;
                int cnt_above = (j == 7) ? above_lane : (sfx[j + 1] + above_lane);
                if (cnt_ge >= rem && cnt_above < rem) {
                    s_sel = bin0 + j;
                    s_rem = rem - cnt_above;
                }
            }
        }
        __syncthreads();
        prefix |= ((unsigned)s_sel) << shift;
    }
    unsigned thr = prefix;           // Kk-th largest key
    int need_eq = s_rem;             // #ties at thr to keep (lowest index first)

    int lane = tid & 31, warp = tid >> 5;
    auto excl_scan = [&](int cnt) -> int {
        int incl = cnt;
#pragma unroll
        for (int off = 1; off < 32; off <<= 1) {
            int v = __shfl_up_sync(0xFFFFFFFFu, incl, off);
            if (lane >= off) incl += v;
        }
        if (lane == 31) warp_sums[warp] = incl;
        __syncthreads();
        if (tid < 32) {
            int v = warp_sums[tid];
#pragma unroll
            for (int off = 1; off < 32; off <<= 1) {
                int t2 = __shfl_up_sync(0xFFFFFFFFu, v, off);
                if (tid >= off) v += t2;
            }
            warp_sums[tid] = v;
        }
        __syncthreads();
        return incl - cnt + (warp ? warp_sums[warp - 1] : 0);
    };

    // tie-rank scan (ascending index over keys == thr)
    int j0 = tid * CHUNK;
    int myties = 0;
#pragma unroll
    for (int u = 0; u < CHUNK; ++u) myties += (skey[j0 + u] == thr) ? 1 : 0;
    int r = excl_scan(myties);

    unsigned selmask = 0u;
    int nsel = 0;
#pragma unroll
    for (int u = 0; u < CHUNK; ++u) {
        unsigned key = skey[j0 + u];
        bool sel = key > thr;
        if (key == thr) { sel = (r < need_eq); ++r; }
        if (sel) { selmask |= (1u << u); ++nsel; }
    }
    __syncthreads();                 // warp_sums reuse
    int pos = excl_scan(nsel);

#pragma unroll
    for (int u = 0; u < CHUNK; ++u) {
        if (selmask & (1u << u)) {
            int j = j0 + u;
            g_sel[obase + pos]  = j;
            g_selw[obase + pos] = tanhf(sval[j]) * (1.f / (float)Kk);
            ++pos;
        }
    }
}

// ---- pooling: dense weighted sum over compacted top-K rows -----------------
__global__ void pool_kernel(const float* __restrict__ x_i, const float* __restrict__ x_d,
                            float* __restrict__ out) {
    constexpr int RPB = Kk / PSPLIT;     // 64 rows per block
    __shared__ int   sidx[RPB];
    __shared__ float swt[RPB];
    int part = blockIdx.x & (PSPLIT - 1);
    int sb   = blockIdx.x >> 4;          // PSPLIT == 16
    int side = sb >> 4;
    int b    = sb & 15;
    const float* x = side ? x_d : x_i;
    int obase = (side * Bb + b) * Kk + part * RPB;
    long long xgbase = (long long)b * NPGv * Cc;

    if (threadIdx.x < RPB) {
        sidx[threadIdx.x] = g_sel[obase + threadIdx.x];
        swt[threadIdx.x]  = g_selw[obase + threadIdx.x];
    }
    __syncthreads();

    int cg = threadIdx.x & 63;           // float4 column group
    int rg = threadIdx.x >> 6;           // row group 0..3
    float4 acc = make_float4(0.f, 0.f, 0.f, 0.f);
#pragma unroll 16
    for (int r = rg; r < RPB; r += 4) {
        int   row = sidx[r];
        float w   = swt[r];
        float4 xv = __ldg(reinterpret_cast<const float4*>(x + xgbase + (long long)row * Cc + cg * 4));
        acc.x += w * xv.x; acc.y += w * xv.y;
        acc.z += w * xv.z; acc.w += w * xv.w;
    }
    float* o = &out[b * (2 * Cc) + side * Cc + cg * 4];
    atomicAdd(reinterpret_cast<float2*>(o),     make_float2(acc.x, acc.y));
    atomicAdd(reinterpret_cast<float2*>(o + 2), make_float2(acc.z, acc.w));
}

// ---- launch ----------------------------------------------------------------
extern "C" void kernel_launch(void* const* d_in, const int* in_sizes, int n_in,
                              void* d_out, int out_size) {
    const float* x_inst     = (const float*)d_in[0];
    const float* x_data     = (const float*)d_in[1];
    const float* w_kqv_inst = (const float*)d_in[2];
    const float* b_kqv_inst = (const float*)d_in[3];
    const float* w_kqv_data = (const float*)d_in[4];
    const float* b_kqv_data = (const float*)d_in[5];
    const float* w_out_inst = (const float*)d_in[6];
    const float* b_out_inst = (const float*)d_in[7];
    const float* w_out_data = (const float*)d_in[8];
    const float* b_out_data = (const float*)d_in[9];
    const float* krel_w     = (const float*)d_in[10];
    const float* krel_b     = (const float*)d_in[11];
    const float* vrel_w     = (const float*)d_in[12];
    const float* vrel_b     = (const float*)d_in[13];
    const float* p_rel      = (const float*)d_in[14];
    const int*   ei_i2d     = (const int*)d_in[15];
    const int*   ei_d2i     = (const int*)d_in[16];
    const int*   ei_i2i     = (const int*)d_in[17];
    float* out = (float*)d_out;

    kqv_kernel<<<(2 * Nn) / 32, 256>>>(x_inst, x_data, w_kqv_inst, b_kqv_inst,
                                       w_kqv_data, b_kqv_data);
    edge_kernel<<<3 * (Ee / 2048), 256>>>(ei_i2d, ei_d2i, ei_i2i, krel_w, krel_b,
                                          vrel_w, vrel_b, p_rel);
    select_kernel<<<2 * Bb, 1024>>>(w_out_inst, b_out_inst, w_out_data, b_out_data, out);
    pool_kernel<<<2 * Bb * PSPLIT, 256>>>(x_inst, x_data, out);
}